// round 7
// baseline (speedup 1.0000x reference)
#include <cuda_runtime.h>
#include <cuda_bf16.h>
#include <cstdint>

// ============================================================================
// CAM: scores = b@c^T (NT), P = softmax(scores), out = P@a + a   per batch.
// B=16, C=1024, HW=1024. Split-bf16 mma.sync GEMMs (hi*hi + hi*lo + lo*hi),
// fp32 accumulate. Base-ISA only (harness targets sm_103, no tcgen05).
// R7: 128x256 CTA tile, 64x64 warp tile (8:1 MMA:LDSM), 3-stage cp.async.
// ============================================================================

#define BATCH 16
#define NDIM 1024

// -------- scratch (device globals; no allocation allowed) --------
__device__ __nv_bfloat16 g_b_hi[(size_t)BATCH * NDIM * NDIM];
__device__ __nv_bfloat16 g_b_lo[(size_t)BATCH * NDIM * NDIM];
__device__ __nv_bfloat16 g_c_hi[(size_t)BATCH * NDIM * NDIM];
__device__ __nv_bfloat16 g_c_lo[(size_t)BATCH * NDIM * NDIM];
__device__ __nv_bfloat16 g_at_hi[(size_t)BATCH * NDIM * NDIM];
__device__ __nv_bfloat16 g_at_lo[(size_t)BATCH * NDIM * NDIM];
__device__ __nv_bfloat16 g_p_hi[(size_t)BATCH * NDIM * NDIM];
__device__ __nv_bfloat16 g_p_lo[(size_t)BATCH * NDIM * NDIM];
__device__ float g_scores[(size_t)BATCH * NDIM * NDIM];

__device__ __forceinline__ uint32_t smem_u32(const void* p) {
    uint32_t a;
    asm("{ .reg .u64 t; cvta.to.shared.u64 t, %1; cvt.u32.u64 %0, t; }"
        : "=r"(a) : "l"(p));
    return a;
}

#define LDSM4(r0, r1, r2, r3, addr) \
    asm volatile("ldmatrix.sync.aligned.m8n8.x4.shared.b16 {%0,%1,%2,%3}, [%4];" \
                 : "=r"(r0), "=r"(r1), "=r"(r2), "=r"(r3) : "r"(addr))

#define MMA16816(d, a, bb0, bb1) \
    asm volatile("mma.sync.aligned.m16n8k16.row.col.f32.bf16.bf16.f32 " \
                 "{%0,%1,%2,%3}, {%4,%5,%6,%7}, {%8,%9}, {%0,%1,%2,%3};" \
                 : "+f"((d)[0]), "+f"((d)[1]), "+f"((d)[2]), "+f"((d)[3]) \
                 : "r"((a)[0]), "r"((a)[1]), "r"((a)[2]), "r"((a)[3]), \
                   "r"(bb0), "r"(bb1))

// 64B-row swizzle: 4 chunks of 16B per row; conflict-free for ldmatrix:
// ch' = ch ^ ((row>>1)&3)
__device__ __forceinline__ uint32_t swz64(uint32_t base, int row, int ch) {
    return base + (uint32_t)(row * 64) +
           (uint32_t)(((ch ^ ((row >> 1) & 3)) & 3) * 16);
}

// ============================================================================
// 1) Fused split fp32 -> bf16 hi/lo for b and c (grid.y selects tensor)
// ============================================================================
__global__ __launch_bounds__(256)
void split_bf16_2(const float* __restrict__ b, const float* __restrict__ c,
                  __nv_bfloat16* __restrict__ b_hi, __nv_bfloat16* __restrict__ b_lo,
                  __nv_bfloat16* __restrict__ c_hi, __nv_bfloat16* __restrict__ c_lo) {
    const float* src = blockIdx.y ? c : b;
    __nv_bfloat16* hi = blockIdx.y ? c_hi : b_hi;
    __nv_bfloat16* lo = blockIdx.y ? c_lo : b_lo;
    size_t i = (size_t)blockIdx.x * blockDim.x + threadIdx.x;
    float4 v = ((const float4*)src)[i];
    __nv_bfloat162 h0 = __floats2bfloat162_rn(v.x, v.y);
    __nv_bfloat162 h1 = __floats2bfloat162_rn(v.z, v.w);
    float lx = v.x - __bfloat162float(h0.x);
    float ly = v.y - __bfloat162float(h0.y);
    float lz = v.z - __bfloat162float(h1.x);
    float lw = v.w - __bfloat162float(h1.y);
    ((__nv_bfloat162*)hi)[i * 2]     = h0;
    ((__nv_bfloat162*)hi)[i * 2 + 1] = h1;
    ((__nv_bfloat162*)lo)[i * 2]     = __floats2bfloat162_rn(lx, ly);
    ((__nv_bfloat162*)lo)[i * 2 + 1] = __floats2bfloat162_rn(lz, lw);
}

// ============================================================================
// 2) Transpose a[b][ch][hw] -> a_t[b][hw][ch], split to bf16 hi/lo
// ============================================================================
__global__ __launch_bounds__(256)
void transpose_split(const float* __restrict__ a, __nv_bfloat16* __restrict__ at_hi,
                     __nv_bfloat16* __restrict__ at_lo) {
    __shared__ float tile[32][33];
    const size_t base = (size_t)blockIdx.z * NDIM * NDIM;
    const int tx = threadIdx.x, ty = threadIdx.y;
    const int x = blockIdx.x * 32 + tx;
    const int y0 = blockIdx.y * 32;
#pragma unroll
    for (int j = 0; j < 4; j++)
        tile[ty + j * 8][tx] = a[base + (size_t)(y0 + ty + j * 8) * NDIM + x];
    __syncthreads();
    const int x2 = blockIdx.y * 32 + tx;
    const int y20 = blockIdx.x * 32;
#pragma unroll
    for (int j = 0; j < 4; j++) {
        float v = tile[tx][ty + j * 8];
        __nv_bfloat16 h = __float2bfloat16(v);
        float l = v - __bfloat162float(h);
        size_t o = base + (size_t)(y20 + ty + j * 8) * NDIM + x2;
        at_hi[o] = h;
        at_lo[o] = __float2bfloat16(l);
    }
}

// ============================================================================
// 3) Row softmax (1024) -> bf16 hi/lo P, shuffle reductions
// ============================================================================
__global__ __launch_bounds__(256)
void cam_softmax(const float* __restrict__ S, __nv_bfloat16* __restrict__ Phi,
                 __nv_bfloat16* __restrict__ Plo) {
    __shared__ float wred[8];
    const size_t row = blockIdx.x;
    const float* p = S + row * NDIM;
    const int tid = threadIdx.x;
    const int lane = tid & 31;
    const int warp = tid >> 5;

    float4 v = *(const float4*)(p + tid * 4);
    float m = fmaxf(fmaxf(v.x, v.y), fmaxf(v.z, v.w));
#pragma unroll
    for (int off = 16; off > 0; off >>= 1)
        m = fmaxf(m, __shfl_xor_sync(0xFFFFFFFFu, m, off));
    if (lane == 0) wred[warp] = m;
    __syncthreads();
    m = wred[0];
#pragma unroll
    for (int w = 1; w < 8; w++) m = fmaxf(m, wred[w]);
    __syncthreads();

    v.x = __expf(v.x - m); v.y = __expf(v.y - m);
    v.z = __expf(v.z - m); v.w = __expf(v.w - m);
    float s = v.x + v.y + v.z + v.w;
#pragma unroll
    for (int off = 16; off > 0; off >>= 1)
        s += __shfl_xor_sync(0xFFFFFFFFu, s, off);
    if (lane == 0) wred[warp] = s;
    __syncthreads();
    s = 0.f;
#pragma unroll
    for (int w = 0; w < 8; w++) s += wred[w];
    const float inv = 1.0f / s;
    v.x *= inv; v.y *= inv; v.z *= inv; v.w *= inv;

    __nv_bfloat162 h0 = __floats2bfloat162_rn(v.x, v.y);
    __nv_bfloat162 h1 = __floats2bfloat162_rn(v.z, v.w);
    float lx = v.x - __bfloat162float(h0.x);
    float ly = v.y - __bfloat162float(h0.y);
    float lz = v.z - __bfloat162float(h1.x);
    float lw = v.w - __bfloat162float(h1.y);
    ((__nv_bfloat162*)(Phi + row * NDIM))[tid * 2]     = h0;
    ((__nv_bfloat162*)(Phi + row * NDIM))[tid * 2 + 1] = h1;
    ((__nv_bfloat162*)(Plo + row * NDIM))[tid * 2]     = __floats2bfloat162_rn(lx, ly);
    ((__nv_bfloat162*)(Plo + row * NDIM))[tid * 2 + 1] = __floats2bfloat162_rn(lz, lw);
}

// ============================================================================
// 4) Split-bf16 NT GEMM via mma.sync. CTA tile 128x256, KC=32, 3-stage
//    cp.async, 8 warps = 2(M) x 4(N), warp tile 64x64, 1 CTA/SM, no reg cap.
// ============================================================================
#define KC 32
#define NCHUNK (NDIM / KC)     // 32
#define TILE_A_B 8192          // A: 128 rows x 64B
#define TILE_B_B 16384         // B: 256 rows x 64B
#define STAGE_B (2 * TILE_A_B + 2 * TILE_B_B)   // 49152
#define NSTAGE 3
#define SMEM_DYN (1024 + NSTAGE * STAGE_B)

template<bool RES>
__global__ __launch_bounds__(256, 1)
void cam_mma_kernel(const __nv_bfloat16* __restrict__ Ahi_g, const __nv_bfloat16* __restrict__ Alo_g,
                    const __nv_bfloat16* __restrict__ Bhi_g, const __nv_bfloat16* __restrict__ Blo_g,
                    const float* __restrict__ resid, float* __restrict__ outp)
{
    extern __shared__ char smem_raw[];
    char* sbase_p = (char*)((((uintptr_t)smem_raw) + 1023) & ~(uintptr_t)1023);
    const uint32_t sbase = smem_u32(sbase_p);

    const int tid = threadIdx.x;
    const int l   = tid & 31;
    const int wid = tid >> 5;
    const int m0  = (wid >> 2) * 64;     // warp M offset within 128
    const int n0  = (wid & 3) * 64;      // warp N offset within 256

    const size_t bofs = (size_t)blockIdx.z * NDIM * NDIM;
    const int row0 = blockIdx.y * 128;
    const int col0 = blockIdx.x * 256;
    const __nv_bfloat16* s0 = Ahi_g + bofs + (size_t)row0 * NDIM;
    const __nv_bfloat16* s1 = Alo_g + bofs + (size_t)row0 * NDIM;
    const __nv_bfloat16* s2 = Bhi_g + bofs + (size_t)col0 * NDIM;
    const __nv_bfloat16* s3 = Blo_g + bofs + (size_t)col0 * NDIM;

    // loader: A tiles 512 slots each, B tiles 1024 slots each (16B per slot)
    auto load_chunk = [&](int c, int buf) {
        const int k0 = c * KC;
        const uint32_t stage = sbase + (uint32_t)buf * STAGE_B;
#pragma unroll
        for (int t = 0; t < 2; t++) {          // A hi/lo: 128 rows
            const __nv_bfloat16* sp = t ? s1 : s0;
            const uint32_t tb = stage + (uint32_t)t * TILE_A_B;
#pragma unroll
            for (int jj = 0; jj < 2; jj++) {
                int slot = tid + 256 * jj;     // 0..511
                int row  = slot >> 2;
                int ch   = slot & 3;
                uint32_t dst = swz64(tb, row, ch);
                const __nv_bfloat16* src = sp + (size_t)row * NDIM + k0 + ch * 8;
                asm volatile("cp.async.cg.shared.global [%0], [%1], 16;"
                             :: "r"(dst), "l"(src));
            }
        }
#pragma unroll
        for (int t = 0; t < 2; t++) {          // B hi/lo: 256 rows
            const __nv_bfloat16* sp = t ? s3 : s2;
            const uint32_t tb = stage + 2 * TILE_A_B + (uint32_t)t * TILE_B_B;
#pragma unroll
            for (int jj = 0; jj < 4; jj++) {
                int slot = tid + 256 * jj;     // 0..1023
                int row  = slot >> 2;
                int ch   = slot & 3;
                uint32_t dst = swz64(tb, row, ch);
                const __nv_bfloat16* src = sp + (size_t)row * NDIM + k0 + ch * 8;
                asm volatile("cp.async.cg.shared.global [%0], [%1], 16;"
                             :: "r"(dst), "l"(src));
            }
        }
        asm volatile("cp.async.commit_group;" ::: "memory");
    };

    float acc[4][8][4];
#pragma unroll
    for (int i = 0; i < 4; i++)
#pragma unroll
        for (int j = 0; j < 8; j++)
#pragma unroll
            for (int q = 0; q < 4; q++) acc[i][j][q] = 0.f;

    const int a_row = l & 15;
    const int a_cs  = l >> 4;                       // 0/1
    const int b_row = (l & 7) + ((l >> 4) << 3);    // 0..15
    const int b_cs  = (l >> 3) & 1;                 // 0/1

    load_chunk(0, 0);
    load_chunk(1, 1);

    int buf = 0;
    for (int c = 0; c < NCHUNK; c++) {
        if (c == NCHUNK - 1) { asm volatile("cp.async.wait_group 0;" ::: "memory"); }
        else                 { asm volatile("cp.async.wait_group 1;" ::: "memory"); }
        __syncthreads();

        if (c + 2 < NCHUNK) {
            int nbuf = buf + 2; if (nbuf >= NSTAGE) nbuf -= NSTAGE;
            load_chunk(c + 2, nbuf);
        }

        const uint32_t st  = sbase + (uint32_t)buf * STAGE_B;
        const uint32_t aHi = st;
        const uint32_t aLo = st + TILE_A_B;
        const uint32_t bHi = st + 2 * TILE_A_B;
        const uint32_t bLo = st + 2 * TILE_A_B + TILE_B_B;

#pragma unroll
        for (int k16 = 0; k16 < 2; k16++) {
            const int chA = 2 * k16 + a_cs;
            const int chB = 2 * k16 + b_cs;

            uint32_t af[4][4];                 // reused: hi pass, then lo pass
            uint32_t bf[8][2], blf[8][2];
#pragma unroll
            for (int i = 0; i < 4; i++) {
                const int r = m0 + i * 16 + a_row;
                LDSM4(af[i][0], af[i][1], af[i][2], af[i][3], swz64(aHi, r, chA));
            }
#pragma unroll
            for (int j = 0; j < 4; j++) {
                const int r = n0 + j * 16 + b_row;
                LDSM4(bf[2*j][0], bf[2*j][1], bf[2*j+1][0], bf[2*j+1][1], swz64(bHi, r, chB));
                LDSM4(blf[2*j][0], blf[2*j][1], blf[2*j+1][0], blf[2*j+1][1], swz64(bLo, r, chB));
            }
#pragma unroll
            for (int i = 0; i < 4; i++)
#pragma unroll
                for (int j = 0; j < 8; j++) {
                    MMA16816(acc[i][j], af[i], bf[j][0], bf[j][1]);
                    MMA16816(acc[i][j], af[i], blf[j][0], blf[j][1]);
                }
            // reload A fragments with lo parts (register reuse)
#pragma unroll
            for (int i = 0; i < 4; i++) {
                const int r = m0 + i * 16 + a_row;
                LDSM4(af[i][0], af[i][1], af[i][2], af[i][3], swz64(aLo, r, chA));
            }
#pragma unroll
            for (int i = 0; i < 4; i++)
#pragma unroll
                for (int j = 0; j < 8; j++)
                    MMA16816(acc[i][j], af[i], bf[j][0], bf[j][1]);
        }
        buf++; if (buf >= NSTAGE) buf = 0;
    }

    // ---- epilogue: regs -> gmem (float2, fused residual) ----
    float* outb = outp + bofs;
    const float* resb = resid + bofs;
    const int er = l >> 2;
    const int ec = (l & 3) * 2;

#pragma unroll
    for (int i = 0; i < 4; i++) {
        const int grow = row0 + m0 + i * 16 + er;
#pragma unroll
        for (int j = 0; j < 8; j++) {
            const int gcol = col0 + n0 + j * 8 + ec;
            size_t o0 = (size_t)grow * NDIM + gcol;
            size_t o1 = (size_t)(grow + 8) * NDIM + gcol;
            float2 v0 = make_float2(acc[i][j][0], acc[i][j][1]);
            float2 v1 = make_float2(acc[i][j][2], acc[i][j][3]);
            if (RES) {
                float2 r0 = *(const float2*)(resb + o0);
                float2 r1 = *(const float2*)(resb + o1);
                v0.x += r0.x; v0.y += r0.y;
                v1.x += r1.x; v1.y += r1.y;
            }
            *(float2*)(outb + o0) = v0;
            *(float2*)(outb + o1) = v1;
        }
    }
}

// ============================================================================
extern "C" void kernel_launch(void* const* d_in, const int* in_sizes, int n_in,
                              void* d_out, int out_size) {
    const float* a = (const float*)d_in[0];
    const float* b = (const float*)d_in[1];
    const float* c = (const float*)d_in[2];
    float* out = (float*)d_out;

    __nv_bfloat16 *b_hi, *b_lo, *c_hi, *c_lo, *at_hi, *at_lo, *p_hi, *p_lo;
    float* scores;
    cudaGetSymbolAddress((void**)&b_hi, g_b_hi);
    cudaGetSymbolAddress((void**)&b_lo, g_b_lo);
    cudaGetSymbolAddress((void**)&c_hi, g_c_hi);
    cudaGetSymbolAddress((void**)&c_lo, g_c_lo);
    cudaGetSymbolAddress((void**)&at_hi, g_at_hi);
    cudaGetSymbolAddress((void**)&at_lo, g_at_lo);
    cudaGetSymbolAddress((void**)&p_hi, g_p_hi);
    cudaGetSymbolAddress((void**)&p_lo, g_p_lo);
    cudaGetSymbolAddress((void**)&scores, g_scores);

    cudaFuncSetAttribute((const void*)cam_mma_kernel<false>,
                         cudaFuncAttributeMaxDynamicSharedMemorySize, SMEM_DYN);
    cudaFuncSetAttribute((const void*)cam_mma_kernel<true>,
                         cudaFuncAttributeMaxDynamicSharedMemorySize, SMEM_DYN);

    const int n4 = (BATCH * NDIM * NDIM) / 4;
    split_bf16_2<<<dim3(n4 / 256, 2), 256>>>(b, c, b_hi, b_lo, c_hi, c_lo);
    transpose_split<<<dim3(32, 32, BATCH), dim3(32, 8)>>>(a, at_hi, at_lo);

    dim3 grid(NDIM / 256, NDIM / 128, BATCH);
    cam_mma_kernel<false><<<grid, 256, SMEM_DYN>>>(b_hi, b_lo, c_hi, c_lo, a, scores);
    cam_softmax<<<BATCH * NDIM, 256>>>(scores, p_hi, p_lo);
    cam_mma_kernel<true><<<grid, 256, SMEM_DYN>>>(p_hi, p_lo, at_hi, at_lo, a, out);
}

// round 8
// speedup vs baseline: 1.0011x; 1.0011x over previous
#include <cuda_runtime.h>
#include <cuda_bf16.h>
#include <cstdint>

// ============================================================================
// CAM: scores = b@c^T (NT), P = softmax(scores), out = P@a + a   per batch.
// B=16, C=1024, HW=1024. Split-bf16 mma.sync GEMMs (hi*hi + hi*lo + lo*hi),
// fp32 accumulate. Base-ISA only (harness targets sm_103, no tcgen05).
// R8: 128x256 CTA tile, 64x64 warp tile, N-half-blocked frags (reg-budgeted),
//     KC=32, 3-stage cp.async, 1 CTA/SM.
// ============================================================================

#define BATCH 16
#define NDIM 1024

// -------- scratch (device globals; no allocation allowed) --------
__device__ __nv_bfloat16 g_b_hi[(size_t)BATCH * NDIM * NDIM];
__device__ __nv_bfloat16 g_b_lo[(size_t)BATCH * NDIM * NDIM];
__device__ __nv_bfloat16 g_c_hi[(size_t)BATCH * NDIM * NDIM];
__device__ __nv_bfloat16 g_c_lo[(size_t)BATCH * NDIM * NDIM];
__device__ __nv_bfloat16 g_at_hi[(size_t)BATCH * NDIM * NDIM];
__device__ __nv_bfloat16 g_at_lo[(size_t)BATCH * NDIM * NDIM];
__device__ __nv_bfloat16 g_p_hi[(size_t)BATCH * NDIM * NDIM];
__device__ __nv_bfloat16 g_p_lo[(size_t)BATCH * NDIM * NDIM];
__device__ float g_scores[(size_t)BATCH * NDIM * NDIM];

__device__ __forceinline__ uint32_t smem_u32(const void* p) {
    uint32_t a;
    asm("{ .reg .u64 t; cvta.to.shared.u64 t, %1; cvt.u32.u64 %0, t; }"
        : "=r"(a) : "l"(p));
    return a;
}

#define LDSM4(r0, r1, r2, r3, addr) \
    asm volatile("ldmatrix.sync.aligned.m8n8.x4.shared.b16 {%0,%1,%2,%3}, [%4];" \
                 : "=r"(r0), "=r"(r1), "=r"(r2), "=r"(r3) : "r"(addr))

#define MMA16816(d, a, bb0, bb1) \
    asm volatile("mma.sync.aligned.m16n8k16.row.col.f32.bf16.bf16.f32 " \
                 "{%0,%1,%2,%3}, {%4,%5,%6,%7}, {%8,%9}, {%0,%1,%2,%3};" \
                 : "+f"((d)[0]), "+f"((d)[1]), "+f"((d)[2]), "+f"((d)[3]) \
                 : "r"((a)[0]), "r"((a)[1]), "r"((a)[2]), "r"((a)[3]), \
                   "r"(bb0), "r"(bb1))

// 64B-row swizzle: 4 chunks of 16B per row; conflict-free for ldmatrix:
// ch' = ch ^ ((row>>1)&3)
__device__ __forceinline__ uint32_t swz64(uint32_t base, int row, int ch) {
    return base + (uint32_t)(row * 64) +
           (uint32_t)(((ch ^ ((row >> 1) & 3)) & 3) * 16);
}

// ============================================================================
// 1) Fused split fp32 -> bf16 hi/lo for b and c (grid.y selects tensor)
// ============================================================================
__global__ __launch_bounds__(256)
void split_bf16_2(const float* __restrict__ b, const float* __restrict__ c,
                  __nv_bfloat16* __restrict__ b_hi, __nv_bfloat16* __restrict__ b_lo,
                  __nv_bfloat16* __restrict__ c_hi, __nv_bfloat16* __restrict__ c_lo) {
    const float* src = blockIdx.y ? c : b;
    __nv_bfloat16* hi = blockIdx.y ? c_hi : b_hi;
    __nv_bfloat16* lo = blockIdx.y ? c_lo : b_lo;
    size_t i = (size_t)blockIdx.x * blockDim.x + threadIdx.x;
    float4 v = ((const float4*)src)[i];
    __nv_bfloat162 h0 = __floats2bfloat162_rn(v.x, v.y);
    __nv_bfloat162 h1 = __floats2bfloat162_rn(v.z, v.w);
    float lx = v.x - __bfloat162float(h0.x);
    float ly = v.y - __bfloat162float(h0.y);
    float lz = v.z - __bfloat162float(h1.x);
    float lw = v.w - __bfloat162float(h1.y);
    ((__nv_bfloat162*)hi)[i * 2]     = h0;
    ((__nv_bfloat162*)hi)[i * 2 + 1] = h1;
    ((__nv_bfloat162*)lo)[i * 2]     = __floats2bfloat162_rn(lx, ly);
    ((__nv_bfloat162*)lo)[i * 2 + 1] = __floats2bfloat162_rn(lz, lw);
}

// ============================================================================
// 2) Transpose a[b][ch][hw] -> a_t[b][hw][ch], split to bf16 hi/lo
// ============================================================================
__global__ __launch_bounds__(256)
void transpose_split(const float* __restrict__ a, __nv_bfloat16* __restrict__ at_hi,
                     __nv_bfloat16* __restrict__ at_lo) {
    __shared__ float tile[32][33];
    const size_t base = (size_t)blockIdx.z * NDIM * NDIM;
    const int tx = threadIdx.x, ty = threadIdx.y;
    const int x = blockIdx.x * 32 + tx;
    const int y0 = blockIdx.y * 32;
#pragma unroll
    for (int j = 0; j < 4; j++)
        tile[ty + j * 8][tx] = a[base + (size_t)(y0 + ty + j * 8) * NDIM + x];
    __syncthreads();
    const int x2 = blockIdx.y * 32 + tx;
    const int y20 = blockIdx.x * 32;
#pragma unroll
    for (int j = 0; j < 4; j++) {
        float v = tile[tx][ty + j * 8];
        __nv_bfloat16 h = __float2bfloat16(v);
        float l = v - __bfloat162float(h);
        size_t o = base + (size_t)(y20 + ty + j * 8) * NDIM + x2;
        at_hi[o] = h;
        at_lo[o] = __float2bfloat16(l);
    }
}

// ============================================================================
// 3) Row softmax (1024) -> bf16 hi/lo P, shuffle reductions
// ============================================================================
__global__ __launch_bounds__(256)
void cam_softmax(const float* __restrict__ S, __nv_bfloat16* __restrict__ Phi,
                 __nv_bfloat16* __restrict__ Plo) {
    __shared__ float wred[8];
    const size_t row = blockIdx.x;
    const float* p = S + row * NDIM;
    const int tid = threadIdx.x;
    const int lane = tid & 31;
    const int warp = tid >> 5;

    float4 v = *(const float4*)(p + tid * 4);
    float m = fmaxf(fmaxf(v.x, v.y), fmaxf(v.z, v.w));
#pragma unroll
    for (int off = 16; off > 0; off >>= 1)
        m = fmaxf(m, __shfl_xor_sync(0xFFFFFFFFu, m, off));
    if (lane == 0) wred[warp] = m;
    __syncthreads();
    m = wred[0];
#pragma unroll
    for (int w = 1; w < 8; w++) m = fmaxf(m, wred[w]);
    __syncthreads();

    v.x = __expf(v.x - m); v.y = __expf(v.y - m);
    v.z = __expf(v.z - m); v.w = __expf(v.w - m);
    float s = v.x + v.y + v.z + v.w;
#pragma unroll
    for (int off = 16; off > 0; off >>= 1)
        s += __shfl_xor_sync(0xFFFFFFFFu, s, off);
    if (lane == 0) wred[warp] = s;
    __syncthreads();
    s = 0.f;
#pragma unroll
    for (int w = 0; w < 8; w++) s += wred[w];
    const float inv = 1.0f / s;
    v.x *= inv; v.y *= inv; v.z *= inv; v.w *= inv;

    __nv_bfloat162 h0 = __floats2bfloat162_rn(v.x, v.y);
    __nv_bfloat162 h1 = __floats2bfloat162_rn(v.z, v.w);
    float lx = v.x - __bfloat162float(h0.x);
    float ly = v.y - __bfloat162float(h0.y);
    float lz = v.z - __bfloat162float(h1.x);
    float lw = v.w - __bfloat162float(h1.y);
    ((__nv_bfloat162*)(Phi + row * NDIM))[tid * 2]     = h0;
    ((__nv_bfloat162*)(Phi + row * NDIM))[tid * 2 + 1] = h1;
    ((__nv_bfloat162*)(Plo + row * NDIM))[tid * 2]     = __floats2bfloat162_rn(lx, ly);
    ((__nv_bfloat162*)(Plo + row * NDIM))[tid * 2 + 1] = __floats2bfloat162_rn(lz, lw);
}

// ============================================================================
// 4) Split-bf16 NT GEMM via mma.sync. CTA tile 128x256, KC=32, 3-stage
//    cp.async, 8 warps = 2(M) x 4(N), warp tile 64x64, N-half-blocked frags.
// ============================================================================
#define KC 32
#define NCHUNK (NDIM / KC)     // 32
#define TILE_A_B 8192          // A: 128 rows x 64B
#define TILE_B_B 16384         // B: 256 rows x 64B
#define STAGE_B (2 * TILE_A_B + 2 * TILE_B_B)   // 49152
#define NSTAGE 3
#define SMEM_DYN (1024 + NSTAGE * STAGE_B)

template<bool RES>
__global__ __launch_bounds__(256, 1)
void cam_mma_kernel(const __nv_bfloat16* __restrict__ Ahi_g, const __nv_bfloat16* __restrict__ Alo_g,
                    const __nv_bfloat16* __restrict__ Bhi_g, const __nv_bfloat16* __restrict__ Blo_g,
                    const float* __restrict__ resid, float* __restrict__ outp)
{
    extern __shared__ char smem_raw[];
    char* sbase_p = (char*)((((uintptr_t)smem_raw) + 1023) & ~(uintptr_t)1023);
    const uint32_t sbase = smem_u32(sbase_p);

    const int tid = threadIdx.x;
    const int l   = tid & 31;
    const int wid = tid >> 5;
    const int m0  = (wid >> 2) * 64;     // warp M offset within 128
    const int n0  = (wid & 3) * 64;      // warp N offset within 256

    const size_t bofs = (size_t)blockIdx.z * NDIM * NDIM;
    const int row0 = blockIdx.y * 128;
    const int col0 = blockIdx.x * 256;
    const __nv_bfloat16* s0 = Ahi_g + bofs + (size_t)row0 * NDIM;
    const __nv_bfloat16* s1 = Alo_g + bofs + (size_t)row0 * NDIM;
    const __nv_bfloat16* s2 = Bhi_g + bofs + (size_t)col0 * NDIM;
    const __nv_bfloat16* s3 = Blo_g + bofs + (size_t)col0 * NDIM;

    auto load_chunk = [&](int c, int buf) {
        const int k0 = c * KC;
        const uint32_t stage = sbase + (uint32_t)buf * STAGE_B;
#pragma unroll
        for (int t = 0; t < 2; t++) {          // A hi/lo: 128 rows
            const __nv_bfloat16* sp = t ? s1 : s0;
            const uint32_t tb = stage + (uint32_t)t * TILE_A_B;
#pragma unroll
            for (int jj = 0; jj < 2; jj++) {
                int slot = tid + 256 * jj;     // 0..511
                int row  = slot >> 2;
                int ch   = slot & 3;
                uint32_t dst = swz64(tb, row, ch);
                const __nv_bfloat16* src = sp + (size_t)row * NDIM + k0 + ch * 8;
                asm volatile("cp.async.cg.shared.global [%0], [%1], 16;"
                             :: "r"(dst), "l"(src));
            }
        }
#pragma unroll
        for (int t = 0; t < 2; t++) {          // B hi/lo: 256 rows
            const __nv_bfloat16* sp = t ? s3 : s2;
            const uint32_t tb = stage + 2 * TILE_A_B + (uint32_t)t * TILE_B_B;
#pragma unroll
            for (int jj = 0; jj < 4; jj++) {
                int slot = tid + 256 * jj;     // 0..1023
                int row  = slot >> 2;
                int ch   = slot & 3;
                uint32_t dst = swz64(tb, row, ch);
                const __nv_bfloat16* src = sp + (size_t)row * NDIM + k0 + ch * 8;
                asm volatile("cp.async.cg.shared.global [%0], [%1], 16;"
                             :: "r"(dst), "l"(src));
            }
        }
        asm volatile("cp.async.commit_group;" ::: "memory");
    };

    float acc[4][8][4];
#pragma unroll
    for (int i = 0; i < 4; i++)
#pragma unroll
        for (int j = 0; j < 8; j++)
#pragma unroll
            for (int q = 0; q < 4; q++) acc[i][j][q] = 0.f;

    const int a_row = l & 15;
    const int a_cs  = l >> 4;                       // 0/1
    const int b_row = (l & 7) + ((l >> 4) << 3);    // 0..15
    const int b_cs  = (l >> 3) & 1;                 // 0/1

    load_chunk(0, 0);
    load_chunk(1, 1);

    int buf = 0;
    for (int c = 0; c < NCHUNK; c++) {
        if (c == NCHUNK - 1) { asm volatile("cp.async.wait_group 0;" ::: "memory"); }
        else                 { asm volatile("cp.async.wait_group 1;" ::: "memory"); }
        __syncthreads();

        if (c + 2 < NCHUNK) {
            int nbuf = buf + 2; if (nbuf >= NSTAGE) nbuf -= NSTAGE;
            load_chunk(c + 2, nbuf);
        }

        const uint32_t st  = sbase + (uint32_t)buf * STAGE_B;
        const uint32_t aHi = st;
        const uint32_t aLo = st + TILE_A_B;
        const uint32_t bHi = st + 2 * TILE_A_B;
        const uint32_t bLo = st + 2 * TILE_A_B + TILE_B_B;

#pragma unroll
        for (int k16 = 0; k16 < 2; k16++) {
            const int chA = 2 * k16 + a_cs;
            const int chB = 2 * k16 + b_cs;

            uint32_t af[4][4];                 // reused: hi pass, then lo pass
#pragma unroll
            for (int i = 0; i < 4; i++) {
                const int r = m0 + i * 16 + a_row;
                LDSM4(af[i][0], af[i][1], af[i][2], af[i][3], swz64(aHi, r, chA));
            }
            // hi pass: Ahi*Bhi + Ahi*Blo, N processed in two halves of 32
#pragma unroll
            for (int jh = 0; jh < 2; jh++) {
                uint32_t bfh[4][2], bfl[4][2];
#pragma unroll
                for (int j2 = 0; j2 < 2; j2++) {
                    const int r = n0 + jh * 32 + j2 * 16 + b_row;
                    LDSM4(bfh[2*j2][0], bfh[2*j2][1], bfh[2*j2+1][0], bfh[2*j2+1][1],
                          swz64(bHi, r, chB));
                    LDSM4(bfl[2*j2][0], bfl[2*j2][1], bfl[2*j2+1][0], bfl[2*j2+1][1],
                          swz64(bLo, r, chB));
                }
#pragma unroll
                for (int i = 0; i < 4; i++)
#pragma unroll
                    for (int j = 0; j < 4; j++) {
                        MMA16816(acc[i][jh*4+j], af[i], bfh[j][0], bfh[j][1]);
                        MMA16816(acc[i][jh*4+j], af[i], bfl[j][0], bfl[j][1]);
                    }
            }
            // lo pass: Alo*Bhi (reload af with lo, re-read Bhi per half)
#pragma unroll
            for (int i = 0; i < 4; i++) {
                const int r = m0 + i * 16 + a_row;
                LDSM4(af[i][0], af[i][1], af[i][2], af[i][3], swz64(aLo, r, chA));
            }
#pragma unroll
            for (int jh = 0; jh < 2; jh++) {
                uint32_t bfh[4][2];
#pragma unroll
                for (int j2 = 0; j2 < 2; j2++) {
                    const int r = n0 + jh * 32 + j2 * 16 + b_row;
                    LDSM4(bfh[2*j2][0], bfh[2*j2][1], bfh[2*j2+1][0], bfh[2*j2+1][1],
                          swz64(bHi, r, chB));
                }
#pragma unroll
                for (int i = 0; i < 4; i++)
#pragma unroll
                    for (int j = 0; j < 4; j++)
                        MMA16816(acc[i][jh*4+j], af[i], bfh[j][0], bfh[j][1]);
            }
        }
        buf++; if (buf >= NSTAGE) buf = 0;
    }

    // ---- epilogue: regs -> gmem (float2, fused residual) ----
    float* outb = outp + bofs;
    const float* resb = resid + bofs;
    const int er = l >> 2;
    const int ec = (l & 3) * 2;

#pragma unroll
    for (int i = 0; i < 4; i++) {
        const int grow = row0 + m0 + i * 16 + er;
#pragma unroll
        for (int j = 0; j < 8; j++) {
            const int gcol = col0 + n0 + j * 8 + ec;
            size_t o0 = (size_t)grow * NDIM + gcol;
            size_t o1 = (size_t)(grow + 8) * NDIM + gcol;
            float2 v0 = make_float2(acc[i][j][0], acc[i][j][1]);
            float2 v1 = make_float2(acc[i][j][2], acc[i][j][3]);
            if (RES) {
                float2 r0 = *(const float2*)(resb + o0);
                float2 r1 = *(const float2*)(resb + o1);
                v0.x += r0.x; v0.y += r0.y;
                v1.x += r1.x; v1.y += r1.y;
            }
            *(float2*)(outb + o0) = v0;
            *(float2*)(outb + o1) = v1;
        }
    }
}

// ============================================================================
extern "C" void kernel_launch(void* const* d_in, const int* in_sizes, int n_in,
                              void* d_out, int out_size) {
    const float* a = (const float*)d_in[0];
    const float* b = (const float*)d_in[1];
    const float* c = (const float*)d_in[2];
    float* out = (float*)d_out;

    __nv_bfloat16 *b_hi, *b_lo, *c_hi, *c_lo, *at_hi, *at_lo, *p_hi, *p_lo;
    float* scores;
    cudaGetSymbolAddress((void**)&b_hi, g_b_hi);
    cudaGetSymbolAddress((void**)&b_lo, g_b_lo);
    cudaGetSymbolAddress((void**)&c_hi, g_c_hi);
    cudaGetSymbolAddress((void**)&c_lo, g_c_lo);
    cudaGetSymbolAddress((void**)&at_hi, g_at_hi);
    cudaGetSymbolAddress((void**)&at_lo, g_at_lo);
    cudaGetSymbolAddress((void**)&p_hi, g_p_hi);
    cudaGetSymbolAddress((void**)&p_lo, g_p_lo);
    cudaGetSymbolAddress((void**)&scores, g_scores);

    cudaFuncSetAttribute((const void*)cam_mma_kernel<false>,
                         cudaFuncAttributeMaxDynamicSharedMemorySize, SMEM_DYN);
    cudaFuncSetAttribute((const void*)cam_mma_kernel<true>,
                         cudaFuncAttributeMaxDynamicSharedMemorySize, SMEM_DYN);

    const int n4 = (BATCH * NDIM * NDIM) / 4;
    split_bf16_2<<<dim3(n4 / 256, 2), 256>>>(b, c, b_hi, b_lo, c_hi, c_lo);
    transpose_split<<<dim3(32, 32, BATCH), dim3(32, 8)>>>(a, at_hi, at_lo);

    dim3 grid(NDIM / 256, NDIM / 128, BATCH);
    cam_mma_kernel<false><<<grid, 256, SMEM_DYN>>>(b_hi, b_lo, c_hi, c_lo, a, scores);
    cam_softmax<<<BATCH * NDIM, 256>>>(scores, p_hi, p_lo);
    cam_mma_kernel<true><<<grid, 256, SMEM_DYN>>>(p_hi, p_lo, at_hi, at_lo, a, out);
}

// round 9
// speedup vs baseline: 1.1646x; 1.1633x over previous
#include <cuda_runtime.h>
#include <cuda_fp16.h>
#include <cstdint>

// ============================================================================
// CAM: scores = b@c^T (NT), P = softmax(scores), out = P@a + a   per batch.
// B=16, C=1024, HW=1024. Split-fp16 mma.sync GEMMs:
//   hi*hi -> f32 accum;  hi*lo + lo*hi -> shared f16 accum (corrections).
// Base-ISA only (harness targets sm_103, no tcgen05).
// R9: fp16 split, f16-acc correction MMAs (tests 2x f16-acc rate hypothesis),
//     KC=64, 3-stage cp.async, 1 sync/chunk, 1 CTA/SM, no reg cap.
// ============================================================================

#define BATCH 16
#define NDIM 1024

// -------- scratch (device globals; no allocation allowed) --------
__device__ __half g_b_hi[(size_t)BATCH * NDIM * NDIM];
__device__ __half g_b_lo[(size_t)BATCH * NDIM * NDIM];
__device__ __half g_c_hi[(size_t)BATCH * NDIM * NDIM];
__device__ __half g_c_lo[(size_t)BATCH * NDIM * NDIM];
__device__ __half g_at_hi[(size_t)BATCH * NDIM * NDIM];
__device__ __half g_at_lo[(size_t)BATCH * NDIM * NDIM];
__device__ __half g_p_hi[(size_t)BATCH * NDIM * NDIM];
__device__ __half g_p_lo[(size_t)BATCH * NDIM * NDIM];
__device__ float g_scores[(size_t)BATCH * NDIM * NDIM];

__device__ __forceinline__ uint32_t smem_u32(const void* p) {
    uint32_t a;
    asm("{ .reg .u64 t; cvta.to.shared.u64 t, %1; cvt.u32.u64 %0, t; }"
        : "=r"(a) : "l"(p));
    return a;
}

#define LDSM4(r0, r1, r2, r3, addr) \
    asm volatile("ldmatrix.sync.aligned.m8n8.x4.shared.b16 {%0,%1,%2,%3}, [%4];" \
                 : "=r"(r0), "=r"(r1), "=r"(r2), "=r"(r3) : "r"(addr))

// f32-accum fp16 MMA (main hi*hi term)
#define MMA_F32(d, a, bb0, bb1) \
    asm volatile("mma.sync.aligned.m16n8k16.row.col.f32.f16.f16.f32 " \
                 "{%0,%1,%2,%3}, {%4,%5,%6,%7}, {%8,%9}, {%0,%1,%2,%3};" \
                 : "+f"((d)[0]), "+f"((d)[1]), "+f"((d)[2]), "+f"((d)[3]) \
                 : "r"((a)[0]), "r"((a)[1]), "r"((a)[2]), "r"((a)[3]), \
                   "r"(bb0), "r"(bb1))

// f16-accum fp16 MMA (correction terms; D/C are 2 regs of __half2)
#define MMA_F16(d, a, bb0, bb1) \
    asm volatile("mma.sync.aligned.m16n8k16.row.col.f16.f16.f16.f16 " \
                 "{%0,%1}, {%2,%3,%4,%5}, {%6,%7}, {%0,%1};" \
                 : "+r"((d)[0]), "+r"((d)[1]) \
                 : "r"((a)[0]), "r"((a)[1]), "r"((a)[2]), "r"((a)[3]), \
                   "r"(bb0), "r"(bb1))

// SW128 swizzle, 128B rows: chunk' = chunk ^ (row & 7)
__device__ __forceinline__ uint32_t swz(uint32_t base, int row, int ch) {
    return base + (uint32_t)(row * 128) + (uint32_t)(((ch ^ (row & 7)) & 7) * 16);
}

// ============================================================================
// 1) Fused split fp32 -> fp16 hi/lo for b and c (grid.y selects tensor)
// ============================================================================
__global__ __launch_bounds__(256)
void split_fp16_2(const float* __restrict__ b, const float* __restrict__ c,
                  __half* __restrict__ b_hi, __half* __restrict__ b_lo,
                  __half* __restrict__ c_hi, __half* __restrict__ c_lo) {
    const float* src = blockIdx.y ? c : b;
    __half* hi = blockIdx.y ? c_hi : b_hi;
    __half* lo = blockIdx.y ? c_lo : b_lo;
    size_t i = (size_t)blockIdx.x * blockDim.x + threadIdx.x;
    float4 v = ((const float4*)src)[i];
    __half hx = __float2half_rn(v.x), hy = __float2half_rn(v.y);
    __half hz = __float2half_rn(v.z), hw = __float2half_rn(v.w);
    float lx = v.x - __half2float(hx);
    float ly = v.y - __half2float(hy);
    float lz = v.z - __half2float(hz);
    float lw = v.w - __half2float(hw);
    ((__half2*)hi)[i * 2]     = __halves2half2(hx, hy);
    ((__half2*)hi)[i * 2 + 1] = __halves2half2(hz, hw);
    ((__half2*)lo)[i * 2]     = __halves2half2(__float2half_rn(lx), __float2half_rn(ly));
    ((__half2*)lo)[i * 2 + 1] = __halves2half2(__float2half_rn(lz), __float2half_rn(lw));
}

// ============================================================================
// 2) Transpose a[b][ch][hw] -> a_t[b][hw][ch], split to fp16 hi/lo
// ============================================================================
__global__ __launch_bounds__(256)
void transpose_split(const float* __restrict__ a, __half* __restrict__ at_hi,
                     __half* __restrict__ at_lo) {
    __shared__ float tile[32][33];
    const size_t base = (size_t)blockIdx.z * NDIM * NDIM;
    const int tx = threadIdx.x, ty = threadIdx.y;
    const int x = blockIdx.x * 32 + tx;
    const int y0 = blockIdx.y * 32;
#pragma unroll
    for (int j = 0; j < 4; j++)
        tile[ty + j * 8][tx] = a[base + (size_t)(y0 + ty + j * 8) * NDIM + x];
    __syncthreads();
    const int x2 = blockIdx.y * 32 + tx;
    const int y20 = blockIdx.x * 32;
#pragma unroll
    for (int j = 0; j < 4; j++) {
        float v = tile[tx][ty + j * 8];
        __half h = __float2half_rn(v);
        float l = v - __half2float(h);
        size_t o = base + (size_t)(y20 + ty + j * 8) * NDIM + x2;
        at_hi[o] = h;
        at_lo[o] = __float2half_rn(l);
    }
}

// ============================================================================
// 3) Row softmax (1024) -> fp16 hi/lo P, shuffle reductions
// ============================================================================
__global__ __launch_bounds__(256)
void cam_softmax(const float* __restrict__ S, __half* __restrict__ Phi,
                 __half* __restrict__ Plo) {
    __shared__ float wred[8];
    const size_t row = blockIdx.x;
    const float* p = S + row * NDIM;
    const int tid = threadIdx.x;
    const int lane = tid & 31;
    const int warp = tid >> 5;

    float4 v = *(const float4*)(p + tid * 4);
    float m = fmaxf(fmaxf(v.x, v.y), fmaxf(v.z, v.w));
#pragma unroll
    for (int off = 16; off > 0; off >>= 1)
        m = fmaxf(m, __shfl_xor_sync(0xFFFFFFFFu, m, off));
    if (lane == 0) wred[warp] = m;
    __syncthreads();
    m = wred[0];
#pragma unroll
    for (int w = 1; w < 8; w++) m = fmaxf(m, wred[w]);
    __syncthreads();

    v.x = __expf(v.x - m); v.y = __expf(v.y - m);
    v.z = __expf(v.z - m); v.w = __expf(v.w - m);
    float s = v.x + v.y + v.z + v.w;
#pragma unroll
    for (int off = 16; off > 0; off >>= 1)
        s += __shfl_xor_sync(0xFFFFFFFFu, s, off);
    if (lane == 0) wred[warp] = s;
    __syncthreads();
    s = 0.f;
#pragma unroll
    for (int w = 0; w < 8; w++) s += wred[w];
    const float inv = 1.0f / s;
    v.x *= inv; v.y *= inv; v.z *= inv; v.w *= inv;

    __half hx = __float2half_rn(v.x), hy = __float2half_rn(v.y);
    __half hz = __float2half_rn(v.z), hw = __float2half_rn(v.w);
    float lx = v.x - __half2float(hx);
    float ly = v.y - __half2float(hy);
    float lz = v.z - __half2float(hz);
    float lw = v.w - __half2float(hw);
    ((__half2*)(Phi + row * NDIM))[tid * 2]     = __halves2half2(hx, hy);
    ((__half2*)(Phi + row * NDIM))[tid * 2 + 1] = __halves2half2(hz, hw);
    ((__half2*)(Plo + row * NDIM))[tid * 2]     =
        __halves2half2(__float2half_rn(lx), __float2half_rn(ly));
    ((__half2*)(Plo + row * NDIM))[tid * 2 + 1] =
        __halves2half2(__float2half_rn(lz), __float2half_rn(lw));
}

// ============================================================================
// 4) Split-fp16 NT GEMM. CTA tile 128x128, KC=64, 3-stage cp.async,
//    8 warps = 2(M) x 4(N), warp tile 64x32.
//    hi*hi -> f32 acc; hi*lo + lo*hi -> shared f16 acc.
// ============================================================================
#define KC 64
#define NCHUNK (NDIM / KC)     // 16
#define TILE_B 16384           // 128 rows x 128B (64 fp16)
#define STAGE_B 65536          // Ahi, Alo, Bhi, Blo
#define NSTAGE 3
#define SMEM_DYN (1024 + NSTAGE * STAGE_B)

template<bool RES>
__global__ __launch_bounds__(256, 1)
void cam_mma_kernel(const __half* __restrict__ Ahi_g, const __half* __restrict__ Alo_g,
                    const __half* __restrict__ Bhi_g, const __half* __restrict__ Blo_g,
                    const float* __restrict__ resid, float* __restrict__ outp)
{
    extern __shared__ char smem_raw[];
    char* sbase_p = (char*)((((uintptr_t)smem_raw) + 1023) & ~(uintptr_t)1023);
    const uint32_t sbase = smem_u32(sbase_p);

    const int tid = threadIdx.x;
    const int l   = tid & 31;
    const int wid = tid >> 5;
    const int m0  = (wid >> 2) * 64;
    const int n0  = (wid & 3) * 32;

    const size_t bofs = (size_t)blockIdx.z * NDIM * NDIM;
    const int row0 = blockIdx.y * 128;
    const int col0 = blockIdx.x * 128;
    const __half* s0 = Ahi_g + bofs + (size_t)row0 * NDIM;
    const __half* s1 = Alo_g + bofs + (size_t)row0 * NDIM;
    const __half* s2 = Bhi_g + bofs + (size_t)col0 * NDIM;
    const __half* s3 = Blo_g + bofs + (size_t)col0 * NDIM;

    auto load_chunk = [&](int c, int buf) {
        const int k0 = c * KC;
        const uint32_t stage = sbase + (uint32_t)buf * STAGE_B;
#pragma unroll
        for (int t = 0; t < 4; t++) {
            const __half* sp = (t == 0) ? s0 : (t == 1) ? s1 : (t == 2) ? s2 : s3;
#pragma unroll
            for (int jj = 0; jj < 4; jj++) {
                int slot = tid + 256 * jj;        // 0..1023
                int row  = slot >> 3;             // 0..127
                int k16  = slot & 7;              // 16B chunk in 128B row
                uint32_t dst = swz(stage + (uint32_t)t * TILE_B, row, k16);
                const __half* src = sp + (size_t)row * NDIM + k0 + k16 * 8;
                asm volatile("cp.async.cg.shared.global [%0], [%1], 16;"
                             :: "r"(dst), "l"(src));
            }
        }
        asm volatile("cp.async.commit_group;" ::: "memory");
    };

    float acc[4][4][4];                 // hi*hi, f32
    uint32_t cacc[4][4][2];             // corrections, packed __half2 x2
#pragma unroll
    for (int i = 0; i < 4; i++)
#pragma unroll
        for (int j = 0; j < 4; j++) {
#pragma unroll
            for (int q = 0; q < 4; q++) acc[i][j][q] = 0.f;
            cacc[i][j][0] = 0u; cacc[i][j][1] = 0u;
        }

    const int a_row = l & 15;
    const int a_cs  = l >> 4;
    const int b_row = (l & 7) + ((l >> 4) << 3);
    const int b_cs  = (l >> 3) & 1;

    load_chunk(0, 0);
    load_chunk(1, 1);

    int buf = 0;
    for (int c = 0; c < NCHUNK; c++) {
        if (c == NCHUNK - 1) { asm volatile("cp.async.wait_group 0;" ::: "memory"); }
        else                 { asm volatile("cp.async.wait_group 1;" ::: "memory"); }
        __syncthreads();

        if (c + 2 < NCHUNK) {
            int nbuf = buf + 2; if (nbuf >= NSTAGE) nbuf -= NSTAGE;
            load_chunk(c + 2, nbuf);
        }

        const uint32_t st  = sbase + (uint32_t)buf * STAGE_B;
        const uint32_t aHi = st;
        const uint32_t aLo = st + TILE_B;
        const uint32_t bHi = st + 2 * TILE_B;
        const uint32_t bLo = st + 3 * TILE_B;

#pragma unroll
        for (int k16 = 0; k16 < 4; k16++) {
            const int chA = 2 * k16 + a_cs;
            const int chB = 2 * k16 + b_cs;

            uint32_t af[4][4];                 // reused: hi pass then lo pass
            uint32_t bh[4][2], bl[4][2];
#pragma unroll
            for (int i = 0; i < 4; i++) {
                const int r = m0 + i * 16 + a_row;
                LDSM4(af[i][0], af[i][1], af[i][2], af[i][3], swz(aHi, r, chA));
            }
#pragma unroll
            for (int j = 0; j < 2; j++) {
                const int r = n0 + j * 16 + b_row;
                LDSM4(bh[2*j][0], bh[2*j][1], bh[2*j+1][0], bh[2*j+1][1], swz(bHi, r, chB));
                LDSM4(bl[2*j][0], bl[2*j][1], bl[2*j+1][0], bl[2*j+1][1], swz(bLo, r, chB));
            }
            // hi*hi (f32 acc) + hi*lo (f16 acc)
#pragma unroll
            for (int i = 0; i < 4; i++)
#pragma unroll
                for (int j = 0; j < 4; j++) {
                    MMA_F32(acc[i][j], af[i], bh[j][0], bh[j][1]);
                    MMA_F16(cacc[i][j], af[i], bl[j][0], bl[j][1]);
                }
            // lo*hi (f16 acc) — reload af with lo parts
#pragma unroll
            for (int i = 0; i < 4; i++) {
                const int r = m0 + i * 16 + a_row;
                LDSM4(af[i][0], af[i][1], af[i][2], af[i][3], swz(aLo, r, chA));
            }
#pragma unroll
            for (int i = 0; i < 4; i++)
#pragma unroll
                for (int j = 0; j < 4; j++)
                    MMA_F16(cacc[i][j], af[i], bh[j][0], bh[j][1]);
        }
        buf++; if (buf >= NSTAGE) buf = 0;
    }

    // ---- epilogue: f32 acc + f16 corrections (+residual) -> gmem ----
    float* outb = outp + bofs;
    const float* resb = resid + bofs;
    const int er = l >> 2;
    const int ec = (l & 3) * 2;

#pragma unroll
    for (int i = 0; i < 4; i++) {
        const int grow = row0 + m0 + i * 16 + er;
#pragma unroll
        for (int j = 0; j < 4; j++) {
            const int gcol = col0 + n0 + j * 8 + ec;
            size_t o0 = (size_t)grow * NDIM + gcol;
            size_t o1 = (size_t)(grow + 8) * NDIM + gcol;
            __half2 c01 = *reinterpret_cast<__half2*>(&cacc[i][j][0]);
            __half2 c23 = *reinterpret_cast<__half2*>(&cacc[i][j][1]);
            float2 v0 = make_float2(acc[i][j][0] + __low2float(c01),
                                    acc[i][j][1] + __high2float(c01));
            float2 v1 = make_float2(acc[i][j][2] + __low2float(c23),
                                    acc[i][j][3] + __high2float(c23));
            if (RES) {
                float2 r0 = *(const float2*)(resb + o0);
                float2 r1 = *(const float2*)(resb + o1);
                v0.x += r0.x; v0.y += r0.y;
                v1.x += r1.x; v1.y += r1.y;
            }
            *(float2*)(outb + o0) = v0;
            *(float2*)(outb + o1) = v1;
        }
    }
}

// ============================================================================
extern "C" void kernel_launch(void* const* d_in, const int* in_sizes, int n_in,
                              void* d_out, int out_size) {
    const float* a = (const float*)d_in[0];
    const float* b = (const float*)d_in[1];
    const float* c = (const float*)d_in[2];
    float* out = (float*)d_out;

    __half *b_hi, *b_lo, *c_hi, *c_lo, *at_hi, *at_lo, *p_hi, *p_lo;
    float* scores;
    cudaGetSymbolAddress((void**)&b_hi, g_b_hi);
    cudaGetSymbolAddress((void**)&b_lo, g_b_lo);
    cudaGetSymbolAddress((void**)&c_hi, g_c_hi);
    cudaGetSymbolAddress((void**)&c_lo, g_c_lo);
    cudaGetSymbolAddress((void**)&at_hi, g_at_hi);
    cudaGetSymbolAddress((void**)&at_lo, g_at_lo);
    cudaGetSymbolAddress((void**)&p_hi, g_p_hi);
    cudaGetSymbolAddress((void**)&p_lo, g_p_lo);
    cudaGetSymbolAddress((void**)&scores, g_scores);

    cudaFuncSetAttribute((const void*)cam_mma_kernel<false>,
                         cudaFuncAttributeMaxDynamicSharedMemorySize, SMEM_DYN);
    cudaFuncSetAttribute((const void*)cam_mma_kernel<true>,
                         cudaFuncAttributeMaxDynamicSharedMemorySize, SMEM_DYN);

    const int n4 = (BATCH * NDIM * NDIM) / 4;
    split_fp16_2<<<dim3(n4 / 256, 2), 256>>>(b, c, b_hi, b_lo, c_hi, c_lo);
    transpose_split<<<dim3(32, 32, BATCH), dim3(32, 8)>>>(a, at_hi, at_lo);

    dim3 grid(8, 8, BATCH);
    cam_mma_kernel<false><<<grid, 256, SMEM_DYN>>>(b_hi, b_lo, c_hi, c_lo, a, scores);
    cam_softmax<<<BATCH * NDIM, 256>>>(scores, p_hi, p_lo);
    cam_mma_kernel<true><<<grid, 256, SMEM_DYN>>>(p_hi, p_lo, at_hi, at_lo, a, out);
}

// round 10
// speedup vs baseline: 1.3123x; 1.1269x over previous
#include <cuda_runtime.h>
#include <cuda_fp16.h>
#include <cstdint>

// ============================================================================
// CAM: scores = b@c^T (NT), P = softmax(scores), out = P@a + a   per batch.
// B=16, C=1024, HW=1024. fp16 split GEMMs:
//   GEMM1 (3-pass): bhi*chi -> f32 acc; bhi*clo + blo*chi -> f16 acc.
//   GEMM2 (2-pass): Phi*ahi -> f32 acc; Phi*alo -> f16 acc. (Plo dropped:
//     |Plo| <= 2^-11 * P, contributes ~1.5e-4 rel err — 6x under gate.)
// Base-ISA only (harness targets sm_103, no tcgen05).
// ============================================================================

#define BATCH 16
#define NDIM 1024

// -------- scratch (device globals; no allocation allowed) --------
__device__ __half g_b_hi[(size_t)BATCH * NDIM * NDIM];
__device__ __half g_b_lo[(size_t)BATCH * NDIM * NDIM];
__device__ __half g_c_hi[(size_t)BATCH * NDIM * NDIM];
__device__ __half g_c_lo[(size_t)BATCH * NDIM * NDIM];
__device__ __half g_at_hi[(size_t)BATCH * NDIM * NDIM];
__device__ __half g_at_lo[(size_t)BATCH * NDIM * NDIM];
__device__ __half g_p_hi[(size_t)BATCH * NDIM * NDIM];
__device__ float g_scores[(size_t)BATCH * NDIM * NDIM];

__device__ __forceinline__ uint32_t smem_u32(const void* p) {
    uint32_t a;
    asm("{ .reg .u64 t; cvta.to.shared.u64 t, %1; cvt.u32.u64 %0, t; }"
        : "=r"(a) : "l"(p));
    return a;
}

#define LDSM4(r0, r1, r2, r3, addr) \
    asm volatile("ldmatrix.sync.aligned.m8n8.x4.shared.b16 {%0,%1,%2,%3}, [%4];" \
                 : "=r"(r0), "=r"(r1), "=r"(r2), "=r"(r3) : "r"(addr))

#define MMA_F32(d, a, bb0, bb1) \
    asm volatile("mma.sync.aligned.m16n8k16.row.col.f32.f16.f16.f32 " \
                 "{%0,%1,%2,%3}, {%4,%5,%6,%7}, {%8,%9}, {%0,%1,%2,%3};" \
                 : "+f"((d)[0]), "+f"((d)[1]), "+f"((d)[2]), "+f"((d)[3]) \
                 : "r"((a)[0]), "r"((a)[1]), "r"((a)[2]), "r"((a)[3]), \
                   "r"(bb0), "r"(bb1))

#define MMA_F16(d, a, bb0, bb1) \
    asm volatile("mma.sync.aligned.m16n8k16.row.col.f16.f16.f16.f16 " \
                 "{%0,%1}, {%2,%3,%4,%5}, {%6,%7}, {%0,%1};" \
                 : "+r"((d)[0]), "+r"((d)[1]) \
                 : "r"((a)[0]), "r"((a)[1]), "r"((a)[2]), "r"((a)[3]), \
                   "r"(bb0), "r"(bb1))

// SW128 swizzle, 128B rows: chunk' = chunk ^ (row & 7)
__device__ __forceinline__ uint32_t swz(uint32_t base, int row, int ch) {
    return base + (uint32_t)(row * 128) + (uint32_t)(((ch ^ (row & 7)) & 7) * 16);
}

// ============================================================================
// 1) Fused split fp32 -> fp16 hi/lo for b and c
// ============================================================================
__global__ __launch_bounds__(256)
void split_fp16_2(const float* __restrict__ b, const float* __restrict__ c,
                  __half* __restrict__ b_hi, __half* __restrict__ b_lo,
                  __half* __restrict__ c_hi, __half* __restrict__ c_lo) {
    const float* src = blockIdx.y ? c : b;
    __half* hi = blockIdx.y ? c_hi : b_hi;
    __half* lo = blockIdx.y ? c_lo : b_lo;
    size_t i = (size_t)blockIdx.x * blockDim.x + threadIdx.x;
    float4 v = ((const float4*)src)[i];
    __half hx = __float2half_rn(v.x), hy = __float2half_rn(v.y);
    __half hz = __float2half_rn(v.z), hw = __float2half_rn(v.w);
    float lx = v.x - __half2float(hx);
    float ly = v.y - __half2float(hy);
    float lz = v.z - __half2float(hz);
    float lw = v.w - __half2float(hw);
    ((__half2*)hi)[i * 2]     = __halves2half2(hx, hy);
    ((__half2*)hi)[i * 2 + 1] = __halves2half2(hz, hw);
    ((__half2*)lo)[i * 2]     = __halves2half2(__float2half_rn(lx), __float2half_rn(ly));
    ((__half2*)lo)[i * 2 + 1] = __halves2half2(__float2half_rn(lz), __float2half_rn(lw));
}

// ============================================================================
// 2) Transpose a[b][ch][hw] -> a_t[b][hw][ch], split to fp16 hi/lo
// ============================================================================
__global__ __launch_bounds__(256)
void transpose_split(const float* __restrict__ a, __half* __restrict__ at_hi,
                     __half* __restrict__ at_lo) {
    __shared__ float tile[32][33];
    const size_t base = (size_t)blockIdx.z * NDIM * NDIM;
    const int tx = threadIdx.x, ty = threadIdx.y;
    const int x = blockIdx.x * 32 + tx;
    const int y0 = blockIdx.y * 32;
#pragma unroll
    for (int j = 0; j < 4; j++)
        tile[ty + j * 8][tx] = a[base + (size_t)(y0 + ty + j * 8) * NDIM + x];
    __syncthreads();
    const int x2 = blockIdx.y * 32 + tx;
    const int y20 = blockIdx.x * 32;
#pragma unroll
    for (int j = 0; j < 4; j++) {
        float v = tile[tx][ty + j * 8];
        __half h = __float2half_rn(v);
        float l = v - __half2float(h);
        size_t o = base + (size_t)(y20 + ty + j * 8) * NDIM + x2;
        at_hi[o] = h;
        at_lo[o] = __float2half_rn(l);
    }
}

// ============================================================================
// 3) Row softmax (1024) -> fp16 P (hi only), shuffle reductions
// ============================================================================
__global__ __launch_bounds__(256)
void cam_softmax(const float* __restrict__ S, __half* __restrict__ Phi) {
    __shared__ float wred[8];
    const size_t row = blockIdx.x;
    const float* p = S + row * NDIM;
    const int tid = threadIdx.x;
    const int lane = tid & 31;
    const int warp = tid >> 5;

    float4 v = *(const float4*)(p + tid * 4);
    float m = fmaxf(fmaxf(v.x, v.y), fmaxf(v.z, v.w));
#pragma unroll
    for (int off = 16; off > 0; off >>= 1)
        m = fmaxf(m, __shfl_xor_sync(0xFFFFFFFFu, m, off));
    if (lane == 0) wred[warp] = m;
    __syncthreads();
    m = wred[0];
#pragma unroll
    for (int w = 1; w < 8; w++) m = fmaxf(m, wred[w]);
    __syncthreads();

    v.x = __expf(v.x - m); v.y = __expf(v.y - m);
    v.z = __expf(v.z - m); v.w = __expf(v.w - m);
    float s = v.x + v.y + v.z + v.w;
#pragma unroll
    for (int off = 16; off > 0; off >>= 1)
        s += __shfl_xor_sync(0xFFFFFFFFu, s, off);
    if (lane == 0) wred[warp] = s;
    __syncthreads();
    s = 0.f;
#pragma unroll
    for (int w = 0; w < 8; w++) s += wred[w];
    const float inv = 1.0f / s;

    ((__half2*)(Phi + row * NDIM))[tid * 2] =
        __halves2half2(__float2half_rn(v.x * inv), __float2half_rn(v.y * inv));
    ((__half2*)(Phi + row * NDIM))[tid * 2 + 1] =
        __halves2half2(__float2half_rn(v.z * inv), __float2half_rn(v.w * inv));
}

// ============================================================================
// 4a) GEMM1: 3-pass split-fp16 NT GEMM (scores). CTA 128x128, KC=64,
//     3-stage cp.async, 8 warps 2x4, warp tile 64x32.
// ============================================================================
#define KC 64
#define NCHUNK (NDIM / KC)     // 16
#define TILE_B 16384           // 128 rows x 128B
#define STAGE_B4 65536         // 4 tiles
#define SMEM_DYN4 (1024 + 3 * STAGE_B4)
#define STAGE_B3 49152         // 3 tiles
#define SMEM_DYN3 (1024 + 3 * STAGE_B3)

__global__ __launch_bounds__(256, 1)
void cam_gemm1(const __half* __restrict__ Ahi_g, const __half* __restrict__ Alo_g,
               const __half* __restrict__ Bhi_g, const __half* __restrict__ Blo_g,
               float* __restrict__ outp)
{
    extern __shared__ char smem_raw[];
    char* sbase_p = (char*)((((uintptr_t)smem_raw) + 1023) & ~(uintptr_t)1023);
    const uint32_t sbase = smem_u32(sbase_p);

    const int tid = threadIdx.x;
    const int l   = tid & 31;
    const int wid = tid >> 5;
    const int m0  = (wid >> 2) * 64;
    const int n0  = (wid & 3) * 32;

    const size_t bofs = (size_t)blockIdx.z * NDIM * NDIM;
    const int row0 = blockIdx.y * 128;
    const int col0 = blockIdx.x * 128;
    const __half* s0 = Ahi_g + bofs + (size_t)row0 * NDIM;
    const __half* s1 = Alo_g + bofs + (size_t)row0 * NDIM;
    const __half* s2 = Bhi_g + bofs + (size_t)col0 * NDIM;
    const __half* s3 = Blo_g + bofs + (size_t)col0 * NDIM;

    auto load_chunk = [&](int c, int buf) {
        const int k0 = c * KC;
        const uint32_t stage = sbase + (uint32_t)buf * STAGE_B4;
#pragma unroll
        for (int t = 0; t < 4; t++) {
            const __half* sp = (t == 0) ? s0 : (t == 1) ? s1 : (t == 2) ? s2 : s3;
#pragma unroll
            for (int jj = 0; jj < 4; jj++) {
                int slot = tid + 256 * jj;
                int row  = slot >> 3;
                int k16  = slot & 7;
                uint32_t dst = swz(stage + (uint32_t)t * TILE_B, row, k16);
                const __half* src = sp + (size_t)row * NDIM + k0 + k16 * 8;
                asm volatile("cp.async.cg.shared.global [%0], [%1], 16;"
                             :: "r"(dst), "l"(src));
            }
        }
        asm volatile("cp.async.commit_group;" ::: "memory");
    };

    float acc[4][4][4];
    uint32_t cacc[4][4][2];
#pragma unroll
    for (int i = 0; i < 4; i++)
#pragma unroll
        for (int j = 0; j < 4; j++) {
#pragma unroll
            for (int q = 0; q < 4; q++) acc[i][j][q] = 0.f;
            cacc[i][j][0] = 0u; cacc[i][j][1] = 0u;
        }

    const int a_row = l & 15;
    const int a_cs  = l >> 4;
    const int b_row = (l & 7) + ((l >> 4) << 3);
    const int b_cs  = (l >> 3) & 1;

    load_chunk(0, 0);
    load_chunk(1, 1);

    int buf = 0;
    for (int c = 0; c < NCHUNK; c++) {
        if (c == NCHUNK - 1) { asm volatile("cp.async.wait_group 0;" ::: "memory"); }
        else                 { asm volatile("cp.async.wait_group 1;" ::: "memory"); }
        __syncthreads();

        if (c + 2 < NCHUNK) {
            int nbuf = buf + 2; if (nbuf >= 3) nbuf -= 3;
            load_chunk(c + 2, nbuf);
        }

        const uint32_t st  = sbase + (uint32_t)buf * STAGE_B4;
        const uint32_t aHi = st;
        const uint32_t aLo = st + TILE_B;
        const uint32_t bHi = st + 2 * TILE_B;
        const uint32_t bLo = st + 3 * TILE_B;

#pragma unroll
        for (int k16 = 0; k16 < 4; k16++) {
            const int chA = 2 * k16 + a_cs;
            const int chB = 2 * k16 + b_cs;

            uint32_t af[4][4];
            uint32_t bh[4][2], bl[4][2];
#pragma unroll
            for (int i = 0; i < 4; i++) {
                const int r = m0 + i * 16 + a_row;
                LDSM4(af[i][0], af[i][1], af[i][2], af[i][3], swz(aHi, r, chA));
            }
#pragma unroll
            for (int j = 0; j < 2; j++) {
                const int r = n0 + j * 16 + b_row;
                LDSM4(bh[2*j][0], bh[2*j][1], bh[2*j+1][0], bh[2*j+1][1], swz(bHi, r, chB));
                LDSM4(bl[2*j][0], bl[2*j][1], bl[2*j+1][0], bl[2*j+1][1], swz(bLo, r, chB));
            }
#pragma unroll
            for (int i = 0; i < 4; i++)
#pragma unroll
                for (int j = 0; j < 4; j++) {
                    MMA_F32(acc[i][j], af[i], bh[j][0], bh[j][1]);
                    MMA_F16(cacc[i][j], af[i], bl[j][0], bl[j][1]);
                }
#pragma unroll
            for (int i = 0; i < 4; i++) {
                const int r = m0 + i * 16 + a_row;
                LDSM4(af[i][0], af[i][1], af[i][2], af[i][3], swz(aLo, r, chA));
            }
#pragma unroll
            for (int i = 0; i < 4; i++)
#pragma unroll
                for (int j = 0; j < 4; j++)
                    MMA_F16(cacc[i][j], af[i], bh[j][0], bh[j][1]);
        }
        buf++; if (buf >= 3) buf = 0;
    }

    float* outb = outp + bofs;
    const int er = l >> 2;
    const int ec = (l & 3) * 2;
#pragma unroll
    for (int i = 0; i < 4; i++) {
        const int grow = row0 + m0 + i * 16 + er;
#pragma unroll
        for (int j = 0; j < 4; j++) {
            const int gcol = col0 + n0 + j * 8 + ec;
            size_t o0 = (size_t)grow * NDIM + gcol;
            size_t o1 = (size_t)(grow + 8) * NDIM + gcol;
            __half2 c01 = *reinterpret_cast<__half2*>(&cacc[i][j][0]);
            __half2 c23 = *reinterpret_cast<__half2*>(&cacc[i][j][1]);
            *(float2*)(outb + o0) = make_float2(acc[i][j][0] + __low2float(c01),
                                                acc[i][j][1] + __high2float(c01));
            *(float2*)(outb + o1) = make_float2(acc[i][j][2] + __low2float(c23),
                                                acc[i][j][3] + __high2float(c23));
        }
    }
}

// ============================================================================
// 4b) GEMM2: 2-pass. out = Phi @ (at_hi + at_lo) + resid. 3 tiles/stage.
// ============================================================================
__global__ __launch_bounds__(256, 1)
void cam_gemm2(const __half* __restrict__ P_g, const __half* __restrict__ Bhi_g,
               const __half* __restrict__ Blo_g, const float* __restrict__ resid,
               float* __restrict__ outp)
{
    extern __shared__ char smem_raw[];
    char* sbase_p = (char*)((((uintptr_t)smem_raw) + 1023) & ~(uintptr_t)1023);
    const uint32_t sbase = smem_u32(sbase_p);

    const int tid = threadIdx.x;
    const int l   = tid & 31;
    const int wid = tid >> 5;
    const int m0  = (wid >> 2) * 64;
    const int n0  = (wid & 3) * 32;

    const size_t bofs = (size_t)blockIdx.z * NDIM * NDIM;
    const int row0 = blockIdx.y * 128;
    const int col0 = blockIdx.x * 128;
    const __half* s0 = P_g   + bofs + (size_t)row0 * NDIM;
    const __half* s2 = Bhi_g + bofs + (size_t)col0 * NDIM;
    const __half* s3 = Blo_g + bofs + (size_t)col0 * NDIM;

    auto load_chunk = [&](int c, int buf) {
        const int k0 = c * KC;
        const uint32_t stage = sbase + (uint32_t)buf * STAGE_B3;
#pragma unroll
        for (int t = 0; t < 3; t++) {
            const __half* sp = (t == 0) ? s0 : (t == 1) ? s2 : s3;
#pragma unroll
            for (int jj = 0; jj < 4; jj++) {
                int slot = tid + 256 * jj;
                int row  = slot >> 3;
                int k16  = slot & 7;
                uint32_t dst = swz(stage + (uint32_t)t * TILE_B, row, k16);
                const __half* src = sp + (size_t)row * NDIM + k0 + k16 * 8;
                asm volatile("cp.async.cg.shared.global [%0], [%1], 16;"
                             :: "r"(dst), "l"(src));
            }
        }
        asm volatile("cp.async.commit_group;" ::: "memory");
    };

    float acc[4][4][4];
    uint32_t cacc[4][4][2];
#pragma unroll
    for (int i = 0; i < 4; i++)
#pragma unroll
        for (int j = 0; j < 4; j++) {
#pragma unroll
            for (int q = 0; q < 4; q++) acc[i][j][q] = 0.f;
            cacc[i][j][0] = 0u; cacc[i][j][1] = 0u;
        }

    const int a_row = l & 15;
    const int a_cs  = l >> 4;
    const int b_row = (l & 7) + ((l >> 4) << 3);
    const int b_cs  = (l >> 3) & 1;

    load_chunk(0, 0);
    load_chunk(1, 1);

    int buf = 0;
    for (int c = 0; c < NCHUNK; c++) {
        if (c == NCHUNK - 1) { asm volatile("cp.async.wait_group 0;" ::: "memory"); }
        else                 { asm volatile("cp.async.wait_group 1;" ::: "memory"); }
        __syncthreads();

        if (c + 2 < NCHUNK) {
            int nbuf = buf + 2; if (nbuf >= 3) nbuf -= 3;
            load_chunk(c + 2, nbuf);
        }

        const uint32_t st  = sbase + (uint32_t)buf * STAGE_B3;
        const uint32_t aP  = st;
        const uint32_t bHi = st + TILE_B;
        const uint32_t bLo = st + 2 * TILE_B;

#pragma unroll
        for (int k16 = 0; k16 < 4; k16++) {
            const int chA = 2 * k16 + a_cs;
            const int chB = 2 * k16 + b_cs;

            uint32_t af[4][4];
            uint32_t bh[4][2], bl[4][2];
#pragma unroll
            for (int i = 0; i < 4; i++) {
                const int r = m0 + i * 16 + a_row;
                LDSM4(af[i][0], af[i][1], af[i][2], af[i][3], swz(aP, r, chA));
            }
#pragma unroll
            for (int j = 0; j < 2; j++) {
                const int r = n0 + j * 16 + b_row;
                LDSM4(bh[2*j][0], bh[2*j][1], bh[2*j+1][0], bh[2*j+1][1], swz(bHi, r, chB));
                LDSM4(bl[2*j][0], bl[2*j][1], bl[2*j+1][0], bl[2*j+1][1], swz(bLo, r, chB));
            }
#pragma unroll
            for (int i = 0; i < 4; i++)
#pragma unroll
                for (int j = 0; j < 4; j++) {
                    MMA_F32(acc[i][j], af[i], bh[j][0], bh[j][1]);
                    MMA_F16(cacc[i][j], af[i], bl[j][0], bl[j][1]);
                }
        }
        buf++; if (buf >= 3) buf = 0;
    }

    float* outb = outp + bofs;
    const float* resb = resid + bofs;
    const int er = l >> 2;
    const int ec = (l & 3) * 2;
#pragma unroll
    for (int i = 0; i < 4; i++) {
        const int grow = row0 + m0 + i * 16 + er;
#pragma unroll
        for (int j = 0; j < 4; j++) {
            const int gcol = col0 + n0 + j * 8 + ec;
            size_t o0 = (size_t)grow * NDIM + gcol;
            size_t o1 = (size_t)(grow + 8) * NDIM + gcol;
            __half2 c01 = *reinterpret_cast<__half2*>(&cacc[i][j][0]);
            __half2 c23 = *reinterpret_cast<__half2*>(&cacc[i][j][1]);
            float2 r0 = *(const float2*)(resb + o0);
            float2 r1 = *(const float2*)(resb + o1);
            *(float2*)(outb + o0) =
                make_float2(acc[i][j][0] + __low2float(c01) + r0.x,
                            acc[i][j][1] + __high2float(c01) + r0.y);
            *(float2*)(outb + o1) =
                make_float2(acc[i][j][2] + __low2float(c23) + r1.x,
                            acc[i][j][3] + __high2float(c23) + r1.y);
        }
    }
}

// ============================================================================
extern "C" void kernel_launch(void* const* d_in, const int* in_sizes, int n_in,
                              void* d_out, int out_size) {
    const float* a = (const float*)d_in[0];
    const float* b = (const float*)d_in[1];
    const float* c = (const float*)d_in[2];
    float* out = (float*)d_out;

    __half *b_hi, *b_lo, *c_hi, *c_lo, *at_hi, *at_lo, *p_hi;
    float* scores;
    cudaGetSymbolAddress((void**)&b_hi, g_b_hi);
    cudaGetSymbolAddress((void**)&b_lo, g_b_lo);
    cudaGetSymbolAddress((void**)&c_hi, g_c_hi);
    cudaGetSymbolAddress((void**)&c_lo, g_c_lo);
    cudaGetSymbolAddress((void**)&at_hi, g_at_hi);
    cudaGetSymbolAddress((void**)&at_lo, g_at_lo);
    cudaGetSymbolAddress((void**)&p_hi, g_p_hi);
    cudaGetSymbolAddress((void**)&scores, g_scores);

    cudaFuncSetAttribute((const void*)cam_gemm1,
                         cudaFuncAttributeMaxDynamicSharedMemorySize, SMEM_DYN4);
    cudaFuncSetAttribute((const void*)cam_gemm2,
                         cudaFuncAttributeMaxDynamicSharedMemorySize, SMEM_DYN3);

    const int n4 = (BATCH * NDIM * NDIM) / 4;
    split_fp16_2<<<dim3(n4 / 256, 2), 256>>>(b, c, b_hi, b_lo, c_hi, c_lo);
    transpose_split<<<dim3(32, 32, BATCH), dim3(32, 8)>>>(a, at_hi, at_lo);

    dim3 grid(8, 8, BATCH);
    cam_gemm1<<<grid, 256, SMEM_DYN4>>>(b_hi, b_lo, c_hi, c_lo, scores);
    cam_softmax<<<BATCH * NDIM, 256>>>(scores, p_hi);
    cam_gemm2<<<grid, 256, SMEM_DYN3>>>(p_hi, at_hi, at_lo, a, out);
}

// round 11
// speedup vs baseline: 1.6088x; 1.2259x over previous
#include <cuda_runtime.h>
#include <cuda_fp16.h>
#include <cstdint>

// ============================================================================
// CAM: scores = b@c^T (NT), P = softmax(scores), out = P@a + a   per batch.
// B=16, C=1024, HW=1024. fp16 split GEMMs:
//   GEMM1 (3-pass): bhi*chi -> f32 acc; bhi*clo + blo*chi -> f16 acc.
//   GEMM2 (1-pass): Phi*ahi -> f32 acc.  (Plo and a_lo dropped: each
//     contributes ~1e-4 rel err; total ~1.5e-4 vs 1e-3 gate.)
// Base-ISA only (harness targets sm_103, no tcgen05).
// ============================================================================

#define BATCH 16
#define NDIM 1024

// -------- scratch (device globals; no allocation allowed) --------
__device__ __half g_b_hi[(size_t)BATCH * NDIM * NDIM];
__device__ __half g_b_lo[(size_t)BATCH * NDIM * NDIM];
__device__ __half g_c_hi[(size_t)BATCH * NDIM * NDIM];
__device__ __half g_c_lo[(size_t)BATCH * NDIM * NDIM];
__device__ __half g_at_hi[(size_t)BATCH * NDIM * NDIM];
__device__ __half g_p_hi[(size_t)BATCH * NDIM * NDIM];
__device__ float g_scores[(size_t)BATCH * NDIM * NDIM];

__device__ __forceinline__ uint32_t smem_u32(const void* p) {
    uint32_t a;
    asm("{ .reg .u64 t; cvta.to.shared.u64 t, %1; cvt.u32.u64 %0, t; }"
        : "=r"(a) : "l"(p));
    return a;
}

#define LDSM4(r0, r1, r2, r3, addr) \
    asm volatile("ldmatrix.sync.aligned.m8n8.x4.shared.b16 {%0,%1,%2,%3}, [%4];" \
                 : "=r"(r0), "=r"(r1), "=r"(r2), "=r"(r3) : "r"(addr))

#define MMA_F32(d, a, bb0, bb1) \
    asm volatile("mma.sync.aligned.m16n8k16.row.col.f32.f16.f16.f32 " \
                 "{%0,%1,%2,%3}, {%4,%5,%6,%7}, {%8,%9}, {%0,%1,%2,%3};" \
                 : "+f"((d)[0]), "+f"((d)[1]), "+f"((d)[2]), "+f"((d)[3]) \
                 : "r"((a)[0]), "r"((a)[1]), "r"((a)[2]), "r"((a)[3]), \
                   "r"(bb0), "r"(bb1))

#define MMA_F16(d, a, bb0, bb1) \
    asm volatile("mma.sync.aligned.m16n8k16.row.col.f16.f16.f16.f16 " \
                 "{%0,%1}, {%2,%3,%4,%5}, {%6,%7}, {%0,%1};" \
                 : "+r"((d)[0]), "+r"((d)[1]) \
                 : "r"((a)[0]), "r"((a)[1]), "r"((a)[2]), "r"((a)[3]), \
                   "r"(bb0), "r"(bb1))

// SW128 swizzle, 128B rows: chunk' = chunk ^ (row & 7)
__device__ __forceinline__ uint32_t swz(uint32_t base, int row, int ch) {
    return base + (uint32_t)(row * 128) + (uint32_t)(((ch ^ (row & 7)) & 7) * 16);
}

// ============================================================================
// 1) Fused split fp32 -> fp16 hi/lo for b and c
// ============================================================================
__global__ __launch_bounds__(256)
void split_fp16_2(const float* __restrict__ b, const float* __restrict__ c,
                  __half* __restrict__ b_hi, __half* __restrict__ b_lo,
                  __half* __restrict__ c_hi, __half* __restrict__ c_lo) {
    const float* src = blockIdx.y ? c : b;
    __half* hi = blockIdx.y ? c_hi : b_hi;
    __half* lo = blockIdx.y ? c_lo : b_lo;
    size_t i = (size_t)blockIdx.x * blockDim.x + threadIdx.x;
    float4 v = ((const float4*)src)[i];
    __half hx = __float2half_rn(v.x), hy = __float2half_rn(v.y);
    __half hz = __float2half_rn(v.z), hw = __float2half_rn(v.w);
    float lx = v.x - __half2float(hx);
    float ly = v.y - __half2float(hy);
    float lz = v.z - __half2float(hz);
    float lw = v.w - __half2float(hw);
    ((__half2*)hi)[i * 2]     = __halves2half2(hx, hy);
    ((__half2*)hi)[i * 2 + 1] = __halves2half2(hz, hw);
    ((__half2*)lo)[i * 2]     = __halves2half2(__float2half_rn(lx), __float2half_rn(ly));
    ((__half2*)lo)[i * 2 + 1] = __halves2half2(__float2half_rn(lz), __float2half_rn(lw));
}

// ============================================================================
// 2) Transpose a[b][ch][hw] -> a_t[b][hw][ch], fp16 hi only
// ============================================================================
__global__ __launch_bounds__(256)
void transpose_half(const float* __restrict__ a, __half* __restrict__ at_hi) {
    __shared__ float tile[32][33];
    const size_t base = (size_t)blockIdx.z * NDIM * NDIM;
    const int tx = threadIdx.x, ty = threadIdx.y;
    const int x = blockIdx.x * 32 + tx;
    const int y0 = blockIdx.y * 32;
#pragma unroll
    for (int j = 0; j < 4; j++)
        tile[ty + j * 8][tx] = a[base + (size_t)(y0 + ty + j * 8) * NDIM + x];
    __syncthreads();
    const int x2 = blockIdx.y * 32 + tx;
    const int y20 = blockIdx.x * 32;
#pragma unroll
    for (int j = 0; j < 4; j++)
        at_hi[base + (size_t)(y20 + ty + j * 8) * NDIM + x2] =
            __float2half_rn(tile[tx][ty + j * 8]);
}

// ============================================================================
// 3) Row softmax (1024) -> fp16 P (hi only), shuffle reductions
// ============================================================================
__global__ __launch_bounds__(256)
void cam_softmax(const float* __restrict__ S, __half* __restrict__ Phi) {
    __shared__ float wred[8];
    const size_t row = blockIdx.x;
    const float* p = S + row * NDIM;
    const int tid = threadIdx.x;
    const int lane = tid & 31;
    const int warp = tid >> 5;

    float4 v = *(const float4*)(p + tid * 4);
    float m = fmaxf(fmaxf(v.x, v.y), fmaxf(v.z, v.w));
#pragma unroll
    for (int off = 16; off > 0; off >>= 1)
        m = fmaxf(m, __shfl_xor_sync(0xFFFFFFFFu, m, off));
    if (lane == 0) wred[warp] = m;
    __syncthreads();
    m = wred[0];
#pragma unroll
    for (int w = 1; w < 8; w++) m = fmaxf(m, wred[w]);
    __syncthreads();

    v.x = __expf(v.x - m); v.y = __expf(v.y - m);
    v.z = __expf(v.z - m); v.w = __expf(v.w - m);
    float s = v.x + v.y + v.z + v.w;
#pragma unroll
    for (int off = 16; off > 0; off >>= 1)
        s += __shfl_xor_sync(0xFFFFFFFFu, s, off);
    if (lane == 0) wred[warp] = s;
    __syncthreads();
    s = 0.f;
#pragma unroll
    for (int w = 0; w < 8; w++) s += wred[w];
    const float inv = 1.0f / s;

    ((__half2*)(Phi + row * NDIM))[tid * 2] =
        __halves2half2(__float2half_rn(v.x * inv), __float2half_rn(v.y * inv));
    ((__half2*)(Phi + row * NDIM))[tid * 2 + 1] =
        __halves2half2(__float2half_rn(v.z * inv), __float2half_rn(v.w * inv));
}

// ============================================================================
// 4a) GEMM1: 3-pass split-fp16 NT GEMM (scores). CTA 128x128, KC=64,
//     3-stage cp.async, 8 warps 2x4, warp tile 64x32, 1 CTA/SM.
//     All 4 operand fragment sets loaded up-front per k16 (no WAR reuse).
// ============================================================================
#define KC 64
#define NCHUNK (NDIM / KC)     // 16
#define TILE_B 16384           // 128 rows x 128B
#define STAGE_B4 65536         // 4 tiles
#define SMEM_DYN4 (1024 + 3 * STAGE_B4)
#define STAGE_B2 32768         // 2 tiles
#define SMEM_DYN2 (1024 + 3 * STAGE_B2)

__global__ __launch_bounds__(256, 1)
void cam_gemm1(const __half* __restrict__ Ahi_g, const __half* __restrict__ Alo_g,
               const __half* __restrict__ Bhi_g, const __half* __restrict__ Blo_g,
               float* __restrict__ outp)
{
    extern __shared__ char smem_raw[];
    char* sbase_p = (char*)((((uintptr_t)smem_raw) + 1023) & ~(uintptr_t)1023);
    const uint32_t sbase = smem_u32(sbase_p);

    const int tid = threadIdx.x;
    const int l   = tid & 31;
    const int wid = tid >> 5;
    const int m0  = (wid >> 2) * 64;
    const int n0  = (wid & 3) * 32;

    const size_t bofs = (size_t)blockIdx.z * NDIM * NDIM;
    const int row0 = blockIdx.y * 128;
    const int col0 = blockIdx.x * 128;
    const __half* s0 = Ahi_g + bofs + (size_t)row0 * NDIM;
    const __half* s1 = Alo_g + bofs + (size_t)row0 * NDIM;
    const __half* s2 = Bhi_g + bofs + (size_t)col0 * NDIM;
    const __half* s3 = Blo_g + bofs + (size_t)col0 * NDIM;

    auto load_chunk = [&](int c, int buf) {
        const int k0 = c * KC;
        const uint32_t stage = sbase + (uint32_t)buf * STAGE_B4;
#pragma unroll
        for (int t = 0; t < 4; t++) {
            const __half* sp = (t == 0) ? s0 : (t == 1) ? s1 : (t == 2) ? s2 : s3;
#pragma unroll
            for (int jj = 0; jj < 4; jj++) {
                int slot = tid + 256 * jj;
                int row  = slot >> 3;
                int k16  = slot & 7;
                uint32_t dst = swz(stage + (uint32_t)t * TILE_B, row, k16);
                const __half* src = sp + (size_t)row * NDIM + k0 + k16 * 8;
                asm volatile("cp.async.cg.shared.global [%0], [%1], 16;"
                             :: "r"(dst), "l"(src));
            }
        }
        asm volatile("cp.async.commit_group;" ::: "memory");
    };

    float acc[4][4][4];
    uint32_t cacc[4][4][2];
#pragma unroll
    for (int i = 0; i < 4; i++)
#pragma unroll
        for (int j = 0; j < 4; j++) {
#pragma unroll
            for (int q = 0; q < 4; q++) acc[i][j][q] = 0.f;
            cacc[i][j][0] = 0u; cacc[i][j][1] = 0u;
        }

    const int a_row = l & 15;
    const int a_cs  = l >> 4;
    const int b_row = (l & 7) + ((l >> 4) << 3);
    const int b_cs  = (l >> 3) & 1;

    load_chunk(0, 0);
    load_chunk(1, 1);

    int buf = 0;
    for (int c = 0; c < NCHUNK; c++) {
        if (c == NCHUNK - 1) { asm volatile("cp.async.wait_group 0;" ::: "memory"); }
        else                 { asm volatile("cp.async.wait_group 1;" ::: "memory"); }
        __syncthreads();

        if (c + 2 < NCHUNK) {
            int nbuf = buf + 2; if (nbuf >= 3) nbuf -= 3;
            load_chunk(c + 2, nbuf);
        }

        const uint32_t st  = sbase + (uint32_t)buf * STAGE_B4;
        const uint32_t aHi = st;
        const uint32_t aLo = st + TILE_B;
        const uint32_t bHi = st + 2 * TILE_B;
        const uint32_t bLo = st + 3 * TILE_B;

#pragma unroll
        for (int k16 = 0; k16 < 4; k16++) {
            const int chA = 2 * k16 + a_cs;
            const int chB = 2 * k16 + b_cs;

            // load ALL fragments up-front: lets LDSMs pipeline under MMAs
            uint32_t ah[4][4], al[4][4];
            uint32_t bh[4][2], bl[4][2];
#pragma unroll
            for (int i = 0; i < 4; i++) {
                const int r = m0 + i * 16 + a_row;
                LDSM4(ah[i][0], ah[i][1], ah[i][2], ah[i][3], swz(aHi, r, chA));
                LDSM4(al[i][0], al[i][1], al[i][2], al[i][3], swz(aLo, r, chA));
            }
#pragma unroll
            for (int j = 0; j < 2; j++) {
                const int r = n0 + j * 16 + b_row;
                LDSM4(bh[2*j][0], bh[2*j][1], bh[2*j+1][0], bh[2*j+1][1], swz(bHi, r, chB));
                LDSM4(bl[2*j][0], bl[2*j][1], bl[2*j+1][0], bl[2*j+1][1], swz(bLo, r, chB));
            }
#pragma unroll
            for (int i = 0; i < 4; i++)
#pragma unroll
                for (int j = 0; j < 4; j++) {
                    MMA_F32(acc[i][j], ah[i], bh[j][0], bh[j][1]);
                    MMA_F16(cacc[i][j], ah[i], bl[j][0], bl[j][1]);
                    MMA_F16(cacc[i][j], al[i], bh[j][0], bh[j][1]);
                }
        }
        buf++; if (buf >= 3) buf = 0;
    }

    float* outb = outp + bofs;
    const int er = l >> 2;
    const int ec = (l & 3) * 2;
#pragma unroll
    for (int i = 0; i < 4; i++) {
        const int grow = row0 + m0 + i * 16 + er;
#pragma unroll
        for (int j = 0; j < 4; j++) {
            const int gcol = col0 + n0 + j * 8 + ec;
            size_t o0 = (size_t)grow * NDIM + gcol;
            size_t o1 = (size_t)(grow + 8) * NDIM + gcol;
            __half2 c01 = *reinterpret_cast<__half2*>(&cacc[i][j][0]);
            __half2 c23 = *reinterpret_cast<__half2*>(&cacc[i][j][1]);
            *(float2*)(outb + o0) = make_float2(acc[i][j][0] + __low2float(c01),
                                                acc[i][j][1] + __high2float(c01));
            *(float2*)(outb + o1) = make_float2(acc[i][j][2] + __low2float(c23),
                                                acc[i][j][3] + __high2float(c23));
        }
    }
}

// ============================================================================
// 4b) GEMM2: single-pass. out = Phi @ at_hi + resid. 2 tiles/stage,
//     3 stages (97KB) -> 2 CTAs/SM. regs ~105 (acc 64) fits 128 cap.
// ============================================================================
__global__ __launch_bounds__(256, 2)
void cam_gemm2(const __half* __restrict__ P_g, const __half* __restrict__ Bhi_g,
               const float* __restrict__ resid, float* __restrict__ outp)
{
    extern __shared__ char smem_raw[];
    char* sbase_p = (char*)((((uintptr_t)smem_raw) + 1023) & ~(uintptr_t)1023);
    const uint32_t sbase = smem_u32(sbase_p);

    const int tid = threadIdx.x;
    const int l   = tid & 31;
    const int wid = tid >> 5;
    const int m0  = (wid >> 2) * 64;
    const int n0  = (wid & 3) * 32;

    const size_t bofs = (size_t)blockIdx.z * NDIM * NDIM;
    const int row0 = blockIdx.y * 128;
    const int col0 = blockIdx.x * 128;
    const __half* s0 = P_g   + bofs + (size_t)row0 * NDIM;
    const __half* s2 = Bhi_g + bofs + (size_t)col0 * NDIM;

    auto load_chunk = [&](int c, int buf) {
        const int k0 = c * KC;
        const uint32_t stage = sbase + (uint32_t)buf * STAGE_B2;
#pragma unroll
        for (int t = 0; t < 2; t++) {
            const __half* sp = t ? s2 : s0;
#pragma unroll
            for (int jj = 0; jj < 4; jj++) {
                int slot = tid + 256 * jj;
                int row  = slot >> 3;
                int k16  = slot & 7;
                uint32_t dst = swz(stage + (uint32_t)t * TILE_B, row, k16);
                const __half* src = sp + (size_t)row * NDIM + k0 + k16 * 8;
                asm volatile("cp.async.cg.shared.global [%0], [%1], 16;"
                             :: "r"(dst), "l"(src));
            }
        }
        asm volatile("cp.async.commit_group;" ::: "memory");
    };

    float acc[4][4][4];
#pragma unroll
    for (int i = 0; i < 4; i++)
#pragma unroll
        for (int j = 0; j < 4; j++)
#pragma unroll
            for (int q = 0; q < 4; q++) acc[i][j][q] = 0.f;

    const int a_row = l & 15;
    const int a_cs  = l >> 4;
    const int b_row = (l & 7) + ((l >> 4) << 3);
    const int b_cs  = (l >> 3) & 1;

    load_chunk(0, 0);
    load_chunk(1, 1);

    int buf = 0;
    for (int c = 0; c < NCHUNK; c++) {
        if (c == NCHUNK - 1) { asm volatile("cp.async.wait_group 0;" ::: "memory"); }
        else                 { asm volatile("cp.async.wait_group 1;" ::: "memory"); }
        __syncthreads();

        if (c + 2 < NCHUNK) {
            int nbuf = buf + 2; if (nbuf >= 3) nbuf -= 3;
            load_chunk(c + 2, nbuf);
        }

        const uint32_t st  = sbase + (uint32_t)buf * STAGE_B2;
        const uint32_t aP  = st;
        const uint32_t bHi = st + TILE_B;

#pragma unroll
        for (int k16 = 0; k16 < 4; k16++) {
            const int chA = 2 * k16 + a_cs;
            const int chB = 2 * k16 + b_cs;

            uint32_t af[4][4];
            uint32_t bh[4][2];
#pragma unroll
            for (int i = 0; i < 4; i++) {
                const int r = m0 + i * 16 + a_row;
                LDSM4(af[i][0], af[i][1], af[i][2], af[i][3], swz(aP, r, chA));
            }
#pragma unroll
            for (int j = 0; j < 2; j++) {
                const int r = n0 + j * 16 + b_row;
                LDSM4(bh[2*j][0], bh[2*j][1], bh[2*j+1][0], bh[2*j+1][1], swz(bHi, r, chB));
            }
#pragma unroll
            for (int i = 0; i < 4; i++)
#pragma unroll
                for (int j = 0; j < 4; j++)
                    MMA_F32(acc[i][j], af[i], bh[j][0], bh[j][1]);
        }
        buf++; if (buf >= 3) buf = 0;
    }

    float* outb = outp + bofs;
    const float* resb = resid + bofs;
    const int er = l >> 2;
    const int ec = (l & 3) * 2;
#pragma unroll
    for (int i = 0; i < 4; i++) {
        const int grow = row0 + m0 + i * 16 + er;
#pragma unroll
        for (int j = 0; j < 4; j++) {
            const int gcol = col0 + n0 + j * 8 + ec;
            size_t o0 = (size_t)grow * NDIM + gcol;
            size_t o1 = (size_t)(grow + 8) * NDIM + gcol;
            float2 r0 = *(const float2*)(resb + o0);
            float2 r1 = *(const float2*)(resb + o1);
            *(float2*)(outb + o0) = make_float2(acc[i][j][0] + r0.x,
                                                acc[i][j][1] + r0.y);
            *(float2*)(outb + o1) = make_float2(acc[i][j][2] + r1.x,
                                                acc[i][j][3] + r1.y);
        }
    }
}

// ============================================================================
extern "C" void kernel_launch(void* const* d_in, const int* in_sizes, int n_in,
                              void* d_out, int out_size) {
    const float* a = (const float*)d_in[0];
    const float* b = (const float*)d_in[1];
    const float* c = (const float*)d_in[2];
    float* out = (float*)d_out;

    __half *b_hi, *b_lo, *c_hi, *c_lo, *at_hi, *p_hi;
    float* scores;
    cudaGetSymbolAddress((void**)&b_hi, g_b_hi);
    cudaGetSymbolAddress((void**)&b_lo, g_b_lo);
    cudaGetSymbolAddress((void**)&c_hi, g_c_hi);
    cudaGetSymbolAddress((void**)&c_lo, g_c_lo);
    cudaGetSymbolAddress((void**)&at_hi, g_at_hi);
    cudaGetSymbolAddress((void**)&p_hi, g_p_hi);
    cudaGetSymbolAddress((void**)&scores, g_scores);

    cudaFuncSetAttribute((const void*)cam_gemm1,
                         cudaFuncAttributeMaxDynamicSharedMemorySize, SMEM_DYN4);
    cudaFuncSetAttribute((const void*)cam_gemm2,
                         cudaFuncAttributeMaxDynamicSharedMemorySize, SMEM_DYN2);

    const int n4 = (BATCH * NDIM * NDIM) / 4;
    split_fp16_2<<<dim3(n4 / 256, 2), 256>>>(b, c, b_hi, b_lo, c_hi, c_lo);
    transpose_half<<<dim3(32, 32, BATCH), dim3(32, 8)>>>(a, at_hi);

    dim3 grid(8, 8, BATCH);
    cam_gemm1<<<grid, 256, SMEM_DYN4>>>(b_hi, b_lo, c_hi, c_lo, scores);
    cam_softmax<<<BATCH * NDIM, 256>>>(scores, p_hi);
    cam_gemm2<<<grid, 256, SMEM_DYN2>>>(p_hi, at_hi, a, out);
}

// round 12
// speedup vs baseline: 1.6138x; 1.0031x over previous
#include <cuda_runtime.h>
#include <cuda_fp16.h>
#include <cstdint>

// ============================================================================
// CAM: scores = b@c^T (NT), P = softmax(scores), out = P@a + a   per batch.
// B=16, C=1024, HW=1024.
//   GEMM1 (3-pass, FUSED split): loads fp32 b,c via LDG, converts to fp16
//     hi/lo in registers, STS to swizzled tiles. bhi*chi -> f32 acc;
//     bhi*clo + blo*chi -> f16 acc.
//   GEMM2 (1-pass): Phi*ahi -> f32 acc (Plo, a_lo dropped; ~1.6e-4 rel err).
// Base-ISA only (harness targets sm_103, no tcgen05).
// ============================================================================

#define BATCH 16
#define NDIM 1024

// -------- scratch (device globals; no allocation allowed) --------
__device__ __half g_at_hi[(size_t)BATCH * NDIM * NDIM];
__device__ __half g_p_hi[(size_t)BATCH * NDIM * NDIM];
__device__ float g_scores[(size_t)BATCH * NDIM * NDIM];

__device__ __forceinline__ uint32_t smem_u32(const void* p) {
    uint32_t a;
    asm("{ .reg .u64 t; cvta.to.shared.u64 t, %1; cvt.u32.u64 %0, t; }"
        : "=r"(a) : "l"(p));
    return a;
}

#define LDSM4(r0, r1, r2, r3, addr) \
    asm volatile("ldmatrix.sync.aligned.m8n8.x4.shared.b16 {%0,%1,%2,%3}, [%4];" \
                 : "=r"(r0), "=r"(r1), "=r"(r2), "=r"(r3) : "r"(addr))

#define MMA_F32(d, a, bb0, bb1) \
    asm volatile("mma.sync.aligned.m16n8k16.row.col.f32.f16.f16.f32 " \
                 "{%0,%1,%2,%3}, {%4,%5,%6,%7}, {%8,%9}, {%0,%1,%2,%3};" \
                 : "+f"((d)[0]), "+f"((d)[1]), "+f"((d)[2]), "+f"((d)[3]) \
                 : "r"((a)[0]), "r"((a)[1]), "r"((a)[2]), "r"((a)[3]), \
                   "r"(bb0), "r"(bb1))

#define MMA_F16(d, a, bb0, bb1) \
    asm volatile("mma.sync.aligned.m16n8k16.row.col.f16.f16.f16.f16 " \
                 "{%0,%1}, {%2,%3,%4,%5}, {%6,%7}, {%0,%1};" \
                 : "+r"((d)[0]), "+r"((d)[1]) \
                 : "r"((a)[0]), "r"((a)[1]), "r"((a)[2]), "r"((a)[3]), \
                   "r"(bb0), "r"(bb1))

// 64B-row swizzle (proven R4/R6): ch' = ch ^ ((row>>1)&3), 4x16B chunks/row
__device__ __forceinline__ uint32_t swz64(uint32_t base, int row, int ch) {
    return base + (uint32_t)(row * 64) +
           (uint32_t)(((ch ^ ((row >> 1) & 3)) & 3) * 16);
}
// SW128 swizzle, 128B rows (for GEMM2 tiles): chunk' = chunk ^ (row & 7)
__device__ __forceinline__ uint32_t swz(uint32_t base, int row, int ch) {
    return base + (uint32_t)(row * 128) + (uint32_t)(((ch ^ (row & 7)) & 7) * 16);
}

// ============================================================================
// 1) Transpose a[b][ch][hw] -> a_t[b][hw][ch], fp16 hi only
// ============================================================================
__global__ __launch_bounds__(256)
void transpose_half(const float* __restrict__ a, __half* __restrict__ at_hi) {
    __shared__ float tile[32][33];
    const size_t base = (size_t)blockIdx.z * NDIM * NDIM;
    const int tx = threadIdx.x, ty = threadIdx.y;
    const int x = blockIdx.x * 32 + tx;
    const int y0 = blockIdx.y * 32;
#pragma unroll
    for (int j = 0; j < 4; j++)
        tile[ty + j * 8][tx] = a[base + (size_t)(y0 + ty + j * 8) * NDIM + x];
    __syncthreads();
    const int x2 = blockIdx.y * 32 + tx;
    const int y20 = blockIdx.x * 32;
#pragma unroll
    for (int j = 0; j < 4; j++)
        at_hi[base + (size_t)(y20 + ty + j * 8) * NDIM + x2] =
            __float2half_rn(tile[tx][ty + j * 8]);
}

// ============================================================================
// 2) Row softmax (1024) -> fp16 P (hi only), shuffle reductions
// ============================================================================
__global__ __launch_bounds__(256)
void cam_softmax(const float* __restrict__ S, __half* __restrict__ Phi) {
    __shared__ float wred[8];
    const size_t row = blockIdx.x;
    const float* p = S + row * NDIM;
    const int tid = threadIdx.x;
    const int lane = tid & 31;
    const int warp = tid >> 5;

    float4 v = *(const float4*)(p + tid * 4);
    float m = fmaxf(fmaxf(v.x, v.y), fmaxf(v.z, v.w));
#pragma unroll
    for (int off = 16; off > 0; off >>= 1)
        m = fmaxf(m, __shfl_xor_sync(0xFFFFFFFFu, m, off));
    if (lane == 0) wred[warp] = m;
    __syncthreads();
    m = wred[0];
#pragma unroll
    for (int w = 1; w < 8; w++) m = fmaxf(m, wred[w]);
    __syncthreads();

    v.x = __expf(v.x - m); v.y = __expf(v.y - m);
    v.z = __expf(v.z - m); v.w = __expf(v.w - m);
    float s = v.x + v.y + v.z + v.w;
#pragma unroll
    for (int off = 16; off > 0; off >>= 1)
        s += __shfl_xor_sync(0xFFFFFFFFu, s, off);
    if (lane == 0) wred[warp] = s;
    __syncthreads();
    s = 0.f;
#pragma unroll
    for (int w = 0; w < 8; w++) s += wred[w];
    const float inv = 1.0f / s;

    ((__half2*)(Phi + row * NDIM))[tid * 2] =
        __halves2half2(__float2half_rn(v.x * inv), __float2half_rn(v.y * inv));
    ((__half2*)(Phi + row * NDIM))[tid * 2 + 1] =
        __halves2half2(__float2half_rn(v.z * inv), __float2half_rn(v.w * inv));
}

// ============================================================================
// 3) GEMM1 with fused fp32->fp16 split. CTA 128x128, KC=32, LDG->regs->STS
//    pipeline (3 fp16 tile buffers), 8 warps 2x4, warp tile 64x32, 1 CTA/SM.
// ============================================================================
#define KC1 32
#define NCH1 (NDIM / KC1)      // 32
#define HTILE 8192             // 128 rows x 64B fp16
#define HBUF_B (4 * HTILE)     // bhi, blo, chi, clo = 32 KB
#define SMEM1 (1024 + 3 * HBUF_B)

__global__ __launch_bounds__(256, 1)
void cam_gemm1(const float* __restrict__ bsrc, const float* __restrict__ csrc,
               float* __restrict__ outp)
{
    extern __shared__ char smem_raw[];
    char* sbase_p = (char*)((((uintptr_t)smem_raw) + 1023) & ~(uintptr_t)1023);
    const uint32_t sbase = smem_u32(sbase_p);

    const int tid = threadIdx.x;
    const int l   = tid & 31;
    const int wid = tid >> 5;
    const int m0  = (wid >> 2) * 64;
    const int n0  = (wid & 3) * 32;

    const size_t bofs = (size_t)blockIdx.z * NDIM * NDIM;
    const int row0 = blockIdx.y * 128;
    const int col0 = blockIdx.x * 128;
    const float* gA = bsrc + bofs + (size_t)row0 * NDIM;   // b rows
    const float* gB = csrc + bofs + (size_t)col0 * NDIM;   // c rows

    // per-thread fp32 staging: 8 float4 = one KC1 chunk of both operands
    float4 rbuf[8];
    // slot -> (tensor, row, f4) mapping
    auto ldg_chunk = [&](int c) {
        const int k0 = c * KC1;
#pragma unroll
        for (int j = 0; j < 8; j++) {
            int slot = tid + 256 * j;          // 0..2047
            int tsel = slot >> 10;             // 0: b(A), 1: c(B)
            int row  = (slot >> 3) & 127;
            int f4   = slot & 7;               // float4 index within 32 floats
            const float* src = (tsel ? gB : gA) + (size_t)row * NDIM + k0 + f4 * 4;
            rbuf[j] = *(const float4*)src;
        }
    };
    auto cvt_chunk = [&](int buf) {
        const uint32_t hb = sbase + (uint32_t)buf * HBUF_B;
#pragma unroll
        for (int j = 0; j < 8; j++) {
            int slot = tid + 256 * j;
            int tsel = slot >> 10;
            int row  = (slot >> 3) & 127;
            int f4   = slot & 7;
            float4 v = rbuf[j];
            __half2 h0 = __floats2half2_rn(v.x, v.y);
            __half2 h1 = __floats2half2_rn(v.z, v.w);
            float lx = v.x - __half2float(__low2half(h0));
            float ly = v.y - __half2float(__high2half(h0));
            float lz = v.z - __half2float(__low2half(h1));
            float lw = v.w - __half2float(__high2half(h1));
            __half2 l0 = __floats2half2_rn(lx, ly);
            __half2 l1 = __floats2half2_rn(lz, lw);
            // byte offset of this float4's 4 fp16 within the 64B row
            uint32_t off = swz64(0, row, f4 >> 1) + (uint32_t)(f4 & 1) * 8;
            uint32_t hiT = hb + (uint32_t)(tsel * 2) * HTILE + off;
            uint32_t loT = hiT + HTILE;
            uint32_t h0u = *(uint32_t*)&h0, h1u = *(uint32_t*)&h1;
            uint32_t l0u = *(uint32_t*)&l0, l1u = *(uint32_t*)&l1;
            asm volatile("st.shared.v2.b32 [%0], {%1,%2};"
                         :: "r"(hiT), "r"(h0u), "r"(h1u) : "memory");
            asm volatile("st.shared.v2.b32 [%0], {%1,%2};"
                         :: "r"(loT), "r"(l0u), "r"(l1u) : "memory");
        }
    };

    float acc[4][4][4];
    uint32_t cacc[4][4][2];
#pragma unroll
    for (int i = 0; i < 4; i++)
#pragma unroll
        for (int j = 0; j < 4; j++) {
#pragma unroll
            for (int q = 0; q < 4; q++) acc[i][j][q] = 0.f;
            cacc[i][j][0] = 0u; cacc[i][j][1] = 0u;
        }

    const int a_row = l & 15;
    const int a_cs  = l >> 4;
    const int b_row = (l & 7) + ((l >> 4) << 3);
    const int b_cs  = (l >> 3) & 1;

    // prologue: chunk0 -> hbuf0; chunk1 -> regs
    ldg_chunk(0);
    cvt_chunk(0);
    ldg_chunk(1);
    __syncthreads();

    for (int c = 0; c < NCH1; c++) {
        // convert chunk c+1 (in regs) into its buffer; prefetch c+2
        if (c + 1 < NCH1) cvt_chunk((c + 1) % 3);
        if (c + 2 < NCH1) ldg_chunk(c + 2);

        // compute chunk c
        const uint32_t hb = sbase + (uint32_t)(c % 3) * HBUF_B;
        const uint32_t aHi = hb;
        const uint32_t aLo = hb + HTILE;
        const uint32_t bHi = hb + 2 * HTILE;
        const uint32_t bLo = hb + 3 * HTILE;

#pragma unroll
        for (int k16 = 0; k16 < 2; k16++) {
            const int chA = 2 * k16 + a_cs;
            const int chB = 2 * k16 + b_cs;

            uint32_t ah[4][4], al[4][4];
            uint32_t bh[4][2], bl[4][2];
#pragma unroll
            for (int i = 0; i < 4; i++) {
                const int r = m0 + i * 16 + a_row;
                LDSM4(ah[i][0], ah[i][1], ah[i][2], ah[i][3], swz64(aHi, r, chA));
                LDSM4(al[i][0], al[i][1], al[i][2], al[i][3], swz64(aLo, r, chA));
            }
#pragma unroll
            for (int j = 0; j < 2; j++) {
                const int r = n0 + j * 16 + b_row;
                LDSM4(bh[2*j][0], bh[2*j][1], bh[2*j+1][0], bh[2*j+1][1], swz64(bHi, r, chB));
                LDSM4(bl[2*j][0], bl[2*j][1], bl[2*j+1][0], bl[2*j+1][1], swz64(bLo, r, chB));
            }
#pragma unroll
            for (int i = 0; i < 4; i++)
#pragma unroll
                for (int j = 0; j < 4; j++) {
                    MMA_F32(acc[i][j], ah[i], bh[j][0], bh[j][1]);
                    MMA_F16(cacc[i][j], ah[i], bl[j][0], bl[j][1]);
                    MMA_F16(cacc[i][j], al[i], bh[j][0], bh[j][1]);
                }
        }
        __syncthreads();
    }

    float* outb = outp + bofs;
    const int er = l >> 2;
    const int ec = (l & 3) * 2;
#pragma unroll
    for (int i = 0; i < 4; i++) {
        const int grow = row0 + m0 + i * 16 + er;
#pragma unroll
        for (int j = 0; j < 4; j++) {
            const int gcol = col0 + n0 + j * 8 + ec;
            size_t o0 = (size_t)grow * NDIM + gcol;
            size_t o1 = (size_t)(grow + 8) * NDIM + gcol;
            __half2 c01 = *reinterpret_cast<__half2*>(&cacc[i][j][0]);
            __half2 c23 = *reinterpret_cast<__half2*>(&cacc[i][j][1]);
            *(float2*)(outb + o0) = make_float2(acc[i][j][0] + __low2float(c01),
                                                acc[i][j][1] + __high2float(c01));
            *(float2*)(outb + o1) = make_float2(acc[i][j][2] + __low2float(c23),
                                                acc[i][j][3] + __high2float(c23));
        }
    }
}

// ============================================================================
// 4) GEMM2: single-pass. out = Phi @ at_hi + resid. CTA 128x128, KC=64,
//    2 tiles/stage, 3 stages, 2 CTAs/SM. (Unchanged from R11.)
// ============================================================================
#define KC 64
#define NCHUNK (NDIM / KC)     // 16
#define TILE_B 16384           // 128 rows x 128B
#define STAGE_B2 32768
#define SMEM_DYN2 (1024 + 3 * STAGE_B2)

__global__ __launch_bounds__(256, 2)
void cam_gemm2(const __half* __restrict__ P_g, const __half* __restrict__ Bhi_g,
               const float* __restrict__ resid, float* __restrict__ outp)
{
    extern __shared__ char smem_raw[];
    char* sbase_p = (char*)((((uintptr_t)smem_raw) + 1023) & ~(uintptr_t)1023);
    const uint32_t sbase = smem_u32(sbase_p);

    const int tid = threadIdx.x;
    const int l   = tid & 31;
    const int wid = tid >> 5;
    const int m0  = (wid >> 2) * 64;
    const int n0  = (wid & 3) * 32;

    const size_t bofs = (size_t)blockIdx.z * NDIM * NDIM;
    const int row0 = blockIdx.y * 128;
    const int col0 = blockIdx.x * 128;
    const __half* s0 = P_g   + bofs + (size_t)row0 * NDIM;
    const __half* s2 = Bhi_g + bofs + (size_t)col0 * NDIM;

    auto load_chunk = [&](int c, int buf) {
        const int k0 = c * KC;
        const uint32_t stage = sbase + (uint32_t)buf * STAGE_B2;
#pragma unroll
        for (int t = 0; t < 2; t++) {
            const __half* sp = t ? s2 : s0;
#pragma unroll
            for (int jj = 0; jj < 4; jj++) {
                int slot = tid + 256 * jj;
                int row  = slot >> 3;
                int k16  = slot & 7;
                uint32_t dst = swz(stage + (uint32_t)t * TILE_B, row, k16);
                const __half* src = sp + (size_t)row * NDIM + k0 + k16 * 8;
                asm volatile("cp.async.cg.shared.global [%0], [%1], 16;"
                             :: "r"(dst), "l"(src));
            }
        }
        asm volatile("cp.async.commit_group;" ::: "memory");
    };

    float acc[4][4][4];
#pragma unroll
    for (int i = 0; i < 4; i++)
#pragma unroll
        for (int j = 0; j < 4; j++)
#pragma unroll
            for (int q = 0; q < 4; q++) acc[i][j][q] = 0.f;

    const int a_row = l & 15;
    const int a_cs  = l >> 4;
    const int b_row = (l & 7) + ((l >> 4) << 3);
    const int b_cs  = (l >> 3) & 1;

    load_chunk(0, 0);
    load_chunk(1, 1);

    int buf = 0;
    for (int c = 0; c < NCHUNK; c++) {
        if (c == NCHUNK - 1) { asm volatile("cp.async.wait_group 0;" ::: "memory"); }
        else                 { asm volatile("cp.async.wait_group 1;" ::: "memory"); }
        __syncthreads();

        if (c + 2 < NCHUNK) {
            int nbuf = buf + 2; if (nbuf >= 3) nbuf -= 3;
            load_chunk(c + 2, nbuf);
        }

        const uint32_t st  = sbase + (uint32_t)buf * STAGE_B2;
        const uint32_t aP  = st;
        const uint32_t bHi = st + TILE_B;

#pragma unroll
        for (int k16 = 0; k16 < 4; k16++) {
            const int chA = 2 * k16 + a_cs;
            const int chB = 2 * k16 + b_cs;

            uint32_t af[4][4];
            uint32_t bh[4][2];
#pragma unroll
            for (int i = 0; i < 4; i++) {
                const int r = m0 + i * 16 + a_row;
                LDSM4(af[i][0], af[i][1], af[i][2], af[i][3], swz(aP, r, chA));
            }
#pragma unroll
            for (int j = 0; j < 2; j++) {
                const int r = n0 + j * 16 + b_row;
                LDSM4(bh[2*j][0], bh[2*j][1], bh[2*j+1][0], bh[2*j+1][1], swz(bHi, r, chB));
            }
#pragma unroll
            for (int i = 0; i < 4; i++)
#pragma unroll
                for (int j = 0; j < 4; j++)
                    MMA_F32(acc[i][j], af[i], bh[j][0], bh[j][1]);
        }
        buf++; if (buf >= 3) buf = 0;
    }

    float* outb = outp + bofs;
    const float* resb = resid + bofs;
    const int er = l >> 2;
    const int ec = (l & 3) * 2;
#pragma unroll
    for (int i = 0; i < 4; i++) {
        const int grow = row0 + m0 + i * 16 + er;
#pragma unroll
        for (int j = 0; j < 4; j++) {
            const int gcol = col0 + n0 + j * 8 + ec;
            size_t o0 = (size_t)grow * NDIM + gcol;
            size_t o1 = (size_t)(grow + 8) * NDIM + gcol;
            float2 r0 = *(const float2*)(resb + o0);
            float2 r1 = *(const float2*)(resb + o1);
            *(float2*)(outb + o0) = make_float2(acc[i][j][0] + r0.x,
                                                acc[i][j][1] + r0.y);
            *(float2*)(outb + o1) = make_float2(acc[i][j][2] + r1.x,
                                                acc[i][j][3] + r1.y);
        }
    }
}

// ============================================================================
extern "C" void kernel_launch(void* const* d_in, const int* in_sizes, int n_in,
                              void* d_out, int out_size) {
    const float* a = (const float*)d_in[0];
    const float* b = (const float*)d_in[1];
    const float* c = (const float*)d_in[2];
    float* out = (float*)d_out;

    __half *at_hi, *p_hi;
    float* scores;
    cudaGetSymbolAddress((void**)&at_hi, g_at_hi);
    cudaGetSymbolAddress((void**)&p_hi, g_p_hi);
    cudaGetSymbolAddress((void**)&scores, g_scores);

    cudaFuncSetAttribute((const void*)cam_gemm1,
                         cudaFuncAttributeMaxDynamicSharedMemorySize, SMEM1);
    cudaFuncSetAttribute((const void*)cam_gemm2,
                         cudaFuncAttributeMaxDynamicSharedMemorySize, SMEM_DYN2);

    transpose_half<<<dim3(32, 32, BATCH), dim3(32, 8)>>>(a, at_hi);

    dim3 grid(8, 8, BATCH);
    cam_gemm1<<<grid, 256, SMEM1>>>(b, c, scores);
    cam_softmax<<<BATCH * NDIM, 256>>>(scores, p_hi);
    cam_gemm2<<<grid, 256, SMEM_DYN2>>>(p_hi, at_hi, a, out);
}

// round 13
// speedup vs baseline: 1.6369x; 1.0143x over previous
#include <cuda_runtime.h>
#include <cuda_fp16.h>
#include <cstdint>

// ============================================================================
// CAM: scores = b@c^T (NT), P = softmax(scores), out = P@a + a   per batch.
// B=16, C=1024, HW=1024.
//   GEMM1 (3-pass, fused split): fp32 LDG -> fp16 hi/lo regs -> STS tiles.
//   GEMM2 (1-pass): Phi*ahi -> f32 acc; 2x2 warp grid, 64x64 warp tile
//     (A redundancy x4 -> x2), 128 threads, 2 CTAs/SM.
// Base-ISA only (harness targets sm_103, no tcgen05).
// ============================================================================

#define BATCH 16
#define NDIM 1024

__device__ __half g_at_hi[(size_t)BATCH * NDIM * NDIM];
__device__ __half g_p_hi[(size_t)BATCH * NDIM * NDIM];
__device__ float g_scores[(size_t)BATCH * NDIM * NDIM];

__device__ __forceinline__ uint32_t smem_u32(const void* p) {
    uint32_t a;
    asm("{ .reg .u64 t; cvta.to.shared.u64 t, %1; cvt.u32.u64 %0, t; }"
        : "=r"(a) : "l"(p));
    return a;
}

#define LDSM4(r0, r1, r2, r3, addr) \
    asm volatile("ldmatrix.sync.aligned.m8n8.x4.shared.b16 {%0,%1,%2,%3}, [%4];" \
                 : "=r"(r0), "=r"(r1), "=r"(r2), "=r"(r3) : "r"(addr))

#define MMA_F32(d, a, bb0, bb1) \
    asm volatile("mma.sync.aligned.m16n8k16.row.col.f32.f16.f16.f32 " \
                 "{%0,%1,%2,%3}, {%4,%5,%6,%7}, {%8,%9}, {%0,%1,%2,%3};" \
                 : "+f"((d)[0]), "+f"((d)[1]), "+f"((d)[2]), "+f"((d)[3]) \
                 : "r"((a)[0]), "r"((a)[1]), "r"((a)[2]), "r"((a)[3]), \
                   "r"(bb0), "r"(bb1))

#define MMA_F16(d, a, bb0, bb1) \
    asm volatile("mma.sync.aligned.m16n8k16.row.col.f16.f16.f16.f16 " \
                 "{%0,%1}, {%2,%3,%4,%5}, {%6,%7}, {%0,%1};" \
                 : "+r"((d)[0]), "+r"((d)[1]) \
                 : "r"((a)[0]), "r"((a)[1]), "r"((a)[2]), "r"((a)[3]), \
                   "r"(bb0), "r"(bb1))

__device__ __forceinline__ uint32_t swz64(uint32_t base, int row, int ch) {
    return base + (uint32_t)(row * 64) +
           (uint32_t)(((ch ^ ((row >> 1) & 3)) & 3) * 16);
}
__device__ __forceinline__ uint32_t swz(uint32_t base, int row, int ch) {
    return base + (uint32_t)(row * 128) + (uint32_t)(((ch ^ (row & 7)) & 7) * 16);
}

// ============================================================================
// 1) Transpose a[b][ch][hw] -> a_t[b][hw][ch], fp16 hi only
// ============================================================================
__global__ __launch_bounds__(256)
void transpose_half(const float* __restrict__ a, __half* __restrict__ at_hi) {
    __shared__ float tile[32][33];
    const size_t base = (size_t)blockIdx.z * NDIM * NDIM;
    const int tx = threadIdx.x, ty = threadIdx.y;
    const int x = blockIdx.x * 32 + tx;
    const int y0 = blockIdx.y * 32;
#pragma unroll
    for (int j = 0; j < 4; j++)
        tile[ty + j * 8][tx] = a[base + (size_t)(y0 + ty + j * 8) * NDIM + x];
    __syncthreads();
    const int x2 = blockIdx.y * 32 + tx;
    const int y20 = blockIdx.x * 32;
#pragma unroll
    for (int j = 0; j < 4; j++)
        at_hi[base + (size_t)(y20 + ty + j * 8) * NDIM + x2] =
            __float2half_rn(tile[tx][ty + j * 8]);
}

// ============================================================================
// 2) Row softmax (1024) -> fp16 P (hi only)
// ============================================================================
__global__ __launch_bounds__(256)
void cam_softmax(const float* __restrict__ S, __half* __restrict__ Phi) {
    __shared__ float wred[8];
    const size_t row = blockIdx.x;
    const float* p = S + row * NDIM;
    const int tid = threadIdx.x;
    const int lane = tid & 31;
    const int warp = tid >> 5;

    float4 v = *(const float4*)(p + tid * 4);
    float m = fmaxf(fmaxf(v.x, v.y), fmaxf(v.z, v.w));
#pragma unroll
    for (int off = 16; off > 0; off >>= 1)
        m = fmaxf(m, __shfl_xor_sync(0xFFFFFFFFu, m, off));
    if (lane == 0) wred[warp] = m;
    __syncthreads();
    m = wred[0];
#pragma unroll
    for (int w = 1; w < 8; w++) m = fmaxf(m, wred[w]);
    __syncthreads();

    v.x = __expf(v.x - m); v.y = __expf(v.y - m);
    v.z = __expf(v.z - m); v.w = __expf(v.w - m);
    float s = v.x + v.y + v.z + v.w;
#pragma unroll
    for (int off = 16; off > 0; off >>= 1)
        s += __shfl_xor_sync(0xFFFFFFFFu, s, off);
    if (lane == 0) wred[warp] = s;
    __syncthreads();
    s = 0.f;
#pragma unroll
    for (int w = 0; w < 8; w++) s += wred[w];
    const float inv = 1.0f / s;

    ((__half2*)(Phi + row * NDIM))[tid * 2] =
        __halves2half2(__float2half_rn(v.x * inv), __float2half_rn(v.y * inv));
    ((__half2*)(Phi + row * NDIM))[tid * 2 + 1] =
        __halves2half2(__float2half_rn(v.z * inv), __float2half_rn(v.w * inv));
}

// ============================================================================
// 3) GEMM1 with fused fp32->fp16 split (unchanged from R12). KC=32.
// ============================================================================
#define KC1 32
#define NCH1 (NDIM / KC1)
#define HTILE 8192
#define HBUF_B (4 * HTILE)
#define SMEM1 (1024 + 3 * HBUF_B)

__global__ __launch_bounds__(256, 1)
void cam_gemm1(const float* __restrict__ bsrc, const float* __restrict__ csrc,
               float* __restrict__ outp)
{
    extern __shared__ char smem_raw[];
    char* sbase_p = (char*)((((uintptr_t)smem_raw) + 1023) & ~(uintptr_t)1023);
    const uint32_t sbase = smem_u32(sbase_p);

    const int tid = threadIdx.x;
    const int l   = tid & 31;
    const int wid = tid >> 5;
    const int m0  = (wid >> 2) * 64;
    const int n0  = (wid & 3) * 32;

    const size_t bofs = (size_t)blockIdx.z * NDIM * NDIM;
    const int row0 = blockIdx.y * 128;
    const int col0 = blockIdx.x * 128;
    const float* gA = bsrc + bofs + (size_t)row0 * NDIM;
    const float* gB = csrc + bofs + (size_t)col0 * NDIM;

    float4 rbuf[8];
    auto ldg_chunk = [&](int c) {
        const int k0 = c * KC1;
#pragma unroll
        for (int j = 0; j < 8; j++) {
            int slot = tid + 256 * j;
            int tsel = slot >> 10;
            int row  = (slot >> 3) & 127;
            int f4   = slot & 7;
            const float* src = (tsel ? gB : gA) + (size_t)row * NDIM + k0 + f4 * 4;
            rbuf[j] = *(const float4*)src;
        }
    };
    auto cvt_chunk = [&](int buf) {
        const uint32_t hb = sbase + (uint32_t)buf * HBUF_B;
#pragma unroll
        for (int j = 0; j < 8; j++) {
            int slot = tid + 256 * j;
            int tsel = slot >> 10;
            int row  = (slot >> 3) & 127;
            int f4   = slot & 7;
            float4 v = rbuf[j];
            __half2 h0 = __floats2half2_rn(v.x, v.y);
            __half2 h1 = __floats2half2_rn(v.z, v.w);
            float lx = v.x - __half2float(__low2half(h0));
            float ly = v.y - __half2float(__high2half(h0));
            float lz = v.z - __half2float(__low2half(h1));
            float lw = v.w - __half2float(__high2half(h1));
            __half2 l0 = __floats2half2_rn(lx, ly);
            __half2 l1 = __floats2half2_rn(lz, lw);
            uint32_t off = swz64(0, row, f4 >> 1) + (uint32_t)(f4 & 1) * 8;
            uint32_t hiT = hb + (uint32_t)(tsel * 2) * HTILE + off;
            uint32_t loT = hiT + HTILE;
            uint32_t h0u = *(uint32_t*)&h0, h1u = *(uint32_t*)&h1;
            uint32_t l0u = *(uint32_t*)&l0, l1u = *(uint32_t*)&l1;
            asm volatile("st.shared.v2.b32 [%0], {%1,%2};"
                         :: "r"(hiT), "r"(h0u), "r"(h1u) : "memory");
            asm volatile("st.shared.v2.b32 [%0], {%1,%2};"
                         :: "r"(loT), "r"(l0u), "r"(l1u) : "memory");
        }
    };

    float acc[4][4][4];
    uint32_t cacc[4][4][2];
#pragma unroll
    for (int i = 0; i < 4; i++)
#pragma unroll
        for (int j = 0; j < 4; j++) {
#pragma unroll
            for (int q = 0; q < 4; q++) acc[i][j][q] = 0.f;
            cacc[i][j][0] = 0u; cacc[i][j][1] = 0u;
        }

    const int a_row = l & 15;
    const int a_cs  = l >> 4;
    const int b_row = (l & 7) + ((l >> 4) << 3);
    const int b_cs  = (l >> 3) & 1;

    ldg_chunk(0);
    cvt_chunk(0);
    ldg_chunk(1);
    __syncthreads();

    for (int c = 0; c < NCH1; c++) {
        if (c + 1 < NCH1) cvt_chunk((c + 1) % 3);
        if (c + 2 < NCH1) ldg_chunk(c + 2);

        const uint32_t hb = sbase + (uint32_t)(c % 3) * HBUF_B;
        const uint32_t aHi = hb;
        const uint32_t aLo = hb + HTILE;
        const uint32_t bHi = hb + 2 * HTILE;
        const uint32_t bLo = hb + 3 * HTILE;

#pragma unroll
        for (int k16 = 0; k16 < 2; k16++) {
            const int chA = 2 * k16 + a_cs;
            const int chB = 2 * k16 + b_cs;

            uint32_t ah[4][4], al[4][4];
            uint32_t bh[4][2], bl[4][2];
#pragma unroll
            for (int i = 0; i < 4; i++) {
                const int r = m0 + i * 16 + a_row;
                LDSM4(ah[i][0], ah[i][1], ah[i][2], ah[i][3], swz64(aHi, r, chA));
                LDSM4(al[i][0], al[i][1], al[i][2], al[i][3], swz64(aLo, r, chA));
            }
#pragma unroll
            for (int j = 0; j < 2; j++) {
                const int r = n0 + j * 16 + b_row;
                LDSM4(bh[2*j][0], bh[2*j][1], bh[2*j+1][0], bh[2*j+1][1], swz64(bHi, r, chB));
                LDSM4(bl[2*j][0], bl[2*j][1], bl[2*j+1][0], bl[2*j+1][1], swz64(bLo, r, chB));
            }
#pragma unroll
            for (int i = 0; i < 4; i++)
#pragma unroll
                for (int j = 0; j < 4; j++) {
                    MMA_F32(acc[i][j], ah[i], bh[j][0], bh[j][1]);
                    MMA_F16(cacc[i][j], ah[i], bl[j][0], bl[j][1]);
                    MMA_F16(cacc[i][j], al[i], bh[j][0], bh[j][1]);
                }
        }
        __syncthreads();
    }

    float* outb = outp + bofs;
    const int er = l >> 2;
    const int ec = (l & 3) * 2;
#pragma unroll
    for (int i = 0; i < 4; i++) {
        const int grow = row0 + m0 + i * 16 + er;
#pragma unroll
        for (int j = 0; j < 4; j++) {
            const int gcol = col0 + n0 + j * 8 + ec;
            size_t o0 = (size_t)grow * NDIM + gcol;
            size_t o1 = (size_t)(grow + 8) * NDIM + gcol;
            __half2 c01 = *reinterpret_cast<__half2*>(&cacc[i][j][0]);
            __half2 c23 = *reinterpret_cast<__half2*>(&cacc[i][j][1]);
            *(float2*)(outb + o0) = make_float2(acc[i][j][0] + __low2float(c01),
                                                acc[i][j][1] + __high2float(c01));
            *(float2*)(outb + o1) = make_float2(acc[i][j][2] + __low2float(c23),
                                                acc[i][j][3] + __high2float(c23));
        }
    }
}

// ============================================================================
// 4) GEMM2: single-pass, 128 threads, 4 warps 2x2, warp tile 64x64.
//    CTA 128x128, KC=64, 2 tiles/stage, 3 stages, 2 CTAs/SM.
// ============================================================================
#define KC 64
#define NCHUNK (NDIM / KC)
#define TILE_B 16384
#define STAGE_B2 32768
#define SMEM_DYN2 (1024 + 3 * STAGE_B2)

__global__ __launch_bounds__(128, 2)
void cam_gemm2(const __half* __restrict__ P_g, const __half* __restrict__ Bhi_g,
               const float* __restrict__ resid, float* __restrict__ outp)
{
    extern __shared__ char smem_raw[];
    char* sbase_p = (char*)((((uintptr_t)smem_raw) + 1023) & ~(uintptr_t)1023);
    const uint32_t sbase = smem_u32(sbase_p);

    const int tid = threadIdx.x;
    const int l   = tid & 31;
    const int wid = tid >> 5;           // 0..3
    const int m0  = (wid >> 1) * 64;    // 2x2 warp grid
    const int n0  = (wid & 1) * 64;

    const size_t bofs = (size_t)blockIdx.z * NDIM * NDIM;
    const int row0 = blockIdx.y * 128;
    const int col0 = blockIdx.x * 128;
    const __half* s0 = P_g   + bofs + (size_t)row0 * NDIM;
    const __half* s2 = Bhi_g + bofs + (size_t)col0 * NDIM;

    // loader: 2048 16B slots per chunk; 128 threads x 16
    auto load_chunk = [&](int c, int buf) {
        const int k0 = c * KC;
        const uint32_t stage = sbase + (uint32_t)buf * STAGE_B2;
#pragma unroll
        for (int jj = 0; jj < 16; jj++) {
            int slot = tid + 128 * jj;       // 0..2047
            int t    = slot >> 10;           // 0: P, 1: Bhi
            int row  = (slot >> 3) & 127;
            int k16  = slot & 7;
            uint32_t dst = swz(stage + (uint32_t)t * TILE_B, row, k16);
            const __half* src = (t ? s2 : s0) + (size_t)row * NDIM + k0 + k16 * 8;
            asm volatile("cp.async.cg.shared.global [%0], [%1], 16;"
                         :: "r"(dst), "l"(src));
        }
        asm volatile("cp.async.commit_group;" ::: "memory");
    };

    float acc[4][8][4];
#pragma unroll
    for (int i = 0; i < 4; i++)
#pragma unroll
        for (int j = 0; j < 8; j++)
#pragma unroll
            for (int q = 0; q < 4; q++) acc[i][j][q] = 0.f;

    const int a_row = l & 15;
    const int a_cs  = l >> 4;
    const int b_row = (l & 7) + ((l >> 4) << 3);
    const int b_cs  = (l >> 3) & 1;

    load_chunk(0, 0);
    load_chunk(1, 1);

    int buf = 0;
    for (int c = 0; c < NCHUNK; c++) {
        if (c == NCHUNK - 1) { asm volatile("cp.async.wait_group 0;" ::: "memory"); }
        else                 { asm volatile("cp.async.wait_group 1;" ::: "memory"); }
        __syncthreads();

        if (c + 2 < NCHUNK) {
            int nbuf = buf + 2; if (nbuf >= 3) nbuf -= 3;
            load_chunk(c + 2, nbuf);
        }

        const uint32_t st  = sbase + (uint32_t)buf * STAGE_B2;
        const uint32_t aP  = st;
        const uint32_t bHi = st + TILE_B;

#pragma unroll
        for (int k16 = 0; k16 < 4; k16++) {
            const int chA = 2 * k16 + a_cs;
            const int chB = 2 * k16 + b_cs;

            uint32_t af[4][4];
            uint32_t bh[8][2];
#pragma unroll
            for (int i = 0; i < 4; i++) {
                const int r = m0 + i * 16 + a_row;
                LDSM4(af[i][0], af[i][1], af[i][2], af[i][3], swz(aP, r, chA));
            }
#pragma unroll
            for (int j = 0; j < 4; j++) {
                const int r = n0 + j * 16 + b_row;
                LDSM4(bh[2*j][0], bh[2*j][1], bh[2*j+1][0], bh[2*j+1][1], swz(bHi, r, chB));
            }
#pragma unroll
            for (int i = 0; i < 4; i++)
#pragma unroll
                for (int j = 0; j < 8; j++)
                    MMA_F32(acc[i][j], af[i], bh[j][0], bh[j][1]);
        }
        buf++; if (buf >= 3) buf = 0;
    }

    float* outb = outp + bofs;
    const float* resb = resid + bofs;
    const int er = l >> 2;
    const int ec = (l & 3) * 2;
#pragma unroll
    for (int i = 0; i < 4; i++) {
        const int grow = row0 + m0 + i * 16 + er;
#pragma unroll
        for (int j = 0; j < 8; j++) {
            const int gcol = col0 + n0 + j * 8 + ec;
            size_t o0 = (size_t)grow * NDIM + gcol;
            size_t o1 = (size_t)(grow + 8) * NDIM + gcol;
            float2 r0 = *(const float2*)(resb + o0);
            float2 r1 = *(const float2*)(resb + o1);
            *(float2*)(outb + o0) = make_float2(acc[i][j][0] + r0.x,
                                                acc[i][j][1] + r0.y);
            *(float2*)(outb + o1) = make_float2(acc[i][j][2] + r1.x,
                                                acc[i][j][3] + r1.y);
        }
    }
}

// ============================================================================
extern "C" void kernel_launch(void* const* d_in, const int* in_sizes, int n_in,
                              void* d_out, int out_size) {
    const float* a = (const float*)d_in[0];
    const float* b = (const float*)d_in[1];
    const float* c = (const float*)d_in[2];
    float* out = (float*)d_out;

    __half *at_hi, *p_hi;
    float* scores;
    cudaGetSymbolAddress((void**)&at_hi, g_at_hi);
    cudaGetSymbolAddress((void**)&p_hi, g_p_hi);
    cudaGetSymbolAddress((void**)&scores, g_scores);

    cudaFuncSetAttribute((const void*)cam_gemm1,
                         cudaFuncAttributeMaxDynamicSharedMemorySize, SMEM1);
    cudaFuncSetAttribute((const void*)cam_gemm2,
                         cudaFuncAttributeMaxDynamicSharedMemorySize, SMEM_DYN2);

    transpose_half<<<dim3(32, 32, BATCH), dim3(32, 8)>>>(a, at_hi);

    dim3 grid(8, 8, BATCH);
    cam_gemm1<<<grid, 256, SMEM1>>>(b, c, scores);
    cam_softmax<<<BATCH * NDIM, 256>>>(scores, p_hi);
    cam_gemm2<<<grid, 128, SMEM_DYN2>>>(p_hi, at_hi, a, out);
}